// round 4
// baseline (speedup 1.0000x reference)
#include <cuda_runtime.h>
#include <math.h>

#define NN 10000
#define NE 200000
#define D  256
#define EPSF 1e-6f

typedef unsigned long long u64;

// ---------------- scratch (device globals: no allocation allowed) ----------
__device__ __align__(128) float g_u[NN * D];
__device__ __align__(128) float g_h[NN * D];
__device__ __align__(128) float g_xp[NN * D];
__device__ __align__(128) float g_xtan[NN * D];
__device__ __align__(128) float g_Q[NN * D];
__device__ __align__(128) float g_P1[NN * D];
__device__ __align__(128) float g_P2[NN * D];
__device__ __align__(128) float g_H[NN * D];
__device__ __align__(128) float g_agg[NN * D];
__device__ __align__(128) float g_S[NN];

// ---------------- packed f32x2 helpers --------------------------------------
__device__ __forceinline__ u64 dup2(float v) {
    u64 r; asm("mov.b64 %0,{%1,%1};" : "=l"(r) : "f"(v)); return r;
}
__device__ __forceinline__ void fma2(u64& c, u64 a, u64 b) {
    asm("fma.rn.f32x2 %0,%1,%2,%0;" : "+l"(c) : "l"(a), "l"(b));
}
__device__ __forceinline__ float2 unpack2(u64 v) {
    float2 f; asm("mov.b64 {%0,%1},%2;" : "=f"(f.x), "=f"(f.y) : "l"(v)); return f;
}

// ---------------- helpers ---------------------------------------------------
__device__ __forceinline__ float blockSum(float v, float* red8) {
    #pragma unroll
    for (int o = 16; o > 0; o >>= 1) v += __shfl_xor_sync(0xffffffffu, v, o);
    __syncthreads();
    if ((threadIdx.x & 31) == 0) red8[threadIdx.x >> 5] = v;
    __syncthreads();
    float r = 0.f;
    #pragma unroll
    for (int i = 0; i < 8; i++) r += red8[i];
    return r;
}

__device__ __forceinline__ float siluf(float x) { return x / (1.f + expf(-x)); }
__device__ __forceinline__ float fsilu(float x) {
    return __fdividef(x, 1.f + __expf(-x));
}

// ---------------- kernel 1: u = logmap0(x) ---------------------------------
__global__ void k_logmap0(const float* __restrict__ x) {
    int idx = blockIdx.x * blockDim.x + threadIdx.x;
    if (idx >= NN * D) return;
    int n = idx >> 8;
    int j = idx & (D - 1);
    float x0 = fmaxf(x[n * D], 1.f + EPSF);
    float outv;
    if (j == 0) {
        outv = 0.f;
    } else {
        float dd = acoshf(x0);
        float sc = dd / sqrtf(x0 * x0 - 1.f);
        outv = sc * x[idx];
    }
    g_u[idx] = outv;
}

// ---------------- SGEMM v4: M-pair accumulators, A transposed in smem -------
// C[M,256] = A[M,256] @ B[256,256]. BM=128, BN=64, BK=16, 128 threads.
// Thread tile: 16 M (8 u64 M-pairs) x 4 N. A pairs come straight from LDS.128;
// only 4 dup2 MOVs per k (B values). 80B LDS per 128 FMA -> fma-pipe bound.
__global__ __launch_bounds__(128, 3) void sgemm_v4(const float* __restrict__ A,
                                                   const float* __restrict__ B,
                                                   float* __restrict__ C, int M) {
    __shared__ float As[2][16 * 132];   // [k][m], stride 132, transposed
    __shared__ float Bs[2][16 * 68];    // [k][n], stride 68 (pad kills conflicts)
    const int K = 256, N = 256;
    int tid = threadIdx.x;
    int tm = tid & 7;           // m-group: rows tm*16 .. tm*16+15
    int tn = tid >> 3;          // n-group: cols tn*4 .. tn*4+3 (0..15)
    int rowBase = blockIdx.y * 128;
    int colBase = blockIdx.x * 64;

    // A staging map: thread owns rows ar, ar+1 and k-halve akh..akh+7
    int ar = (tid & 63) * 2;
    int akh = (tid >> 6) * 8;   // 0 or 8
    const float* Ap0 = A + (size_t)(rowBase + ar) * K + akh;
    const float* Ap1 = Ap0 + K;
    bool ok0 = (rowBase + ar) < M;
    bool ok1 = (rowBase + ar + 1) < M;
    // B staging map: thread owns row br, 8 cols at bc
    int br = tid >> 3;          // 0..15
    int bc = (tid & 7) * 8;
    const float* Bp = B + (size_t)br * N + colBase + bc;

    const float4 z4 = make_float4(0.f, 0.f, 0.f, 0.f);

    // ---- prologue: stage tile kb=0
    float4 a00 = ok0 ? *(const float4*)(Ap0 + 0) : z4;
    float4 a01 = ok0 ? *(const float4*)(Ap0 + 4) : z4;
    float4 a10 = ok1 ? *(const float4*)(Ap1 + 0) : z4;
    float4 a11 = ok1 ? *(const float4*)(Ap1 + 4) : z4;
    float4 bA  = *(const float4*)(Bp);
    float4 bB  = *(const float4*)(Bp + 4);
    {
        float r0[8] = {a00.x, a00.y, a00.z, a00.w, a01.x, a01.y, a01.z, a01.w};
        float r1[8] = {a10.x, a10.y, a10.z, a10.w, a11.x, a11.y, a11.z, a11.w};
        #pragma unroll
        for (int kk = 0; kk < 8; kk++)
            *(float2*)&As[0][(akh + kk) * 132 + ar] = make_float2(r0[kk], r1[kk]);
        *(float4*)&Bs[0][br * 68 + bc]     = bA;
        *(float4*)&Bs[0][br * 68 + bc + 4] = bB;
    }
    __syncthreads();

    u64 acc[8][4];
    #pragma unroll
    for (int i = 0; i < 8; i++)
        #pragma unroll
        for (int j = 0; j < 4; j++) acc[i][j] = 0ull;

    int buf = 0;
    for (int kb = 0; kb < 16; kb++) {
        if (kb < 15) {
            const float* ap0 = Ap0 + (kb + 1) * 16;
            const float* ap1 = Ap1 + (kb + 1) * 16;
            a00 = ok0 ? *(const float4*)(ap0 + 0) : z4;
            a01 = ok0 ? *(const float4*)(ap0 + 4) : z4;
            a10 = ok1 ? *(const float4*)(ap1 + 0) : z4;
            a11 = ok1 ? *(const float4*)(ap1 + 4) : z4;
            bA  = *(const float4*)(Bp + (size_t)(kb + 1) * 16 * N);
            bB  = *(const float4*)(Bp + (size_t)(kb + 1) * 16 * N + 4);
        }
        #pragma unroll
        for (int k = 0; k < 16; k++) {
            const float* Ak = &As[buf][k * 132 + tm * 16];
            ulonglong2 ap0 = *(const ulonglong2*)(Ak + 0);   // m-pairs 0,1
            ulonglong2 ap1 = *(const ulonglong2*)(Ak + 4);   // m-pairs 2,3
            ulonglong2 ap2 = *(const ulonglong2*)(Ak + 8);   // m-pairs 4,5
            ulonglong2 ap3 = *(const ulonglong2*)(Ak + 12);  // m-pairs 6,7
            float4 bv = *(const float4*)&Bs[buf][k * 68 + tn * 4];
            u64 b0 = dup2(bv.x), b1 = dup2(bv.y), b2 = dup2(bv.z), b3 = dup2(bv.w);
            fma2(acc[0][0], ap0.x, b0); fma2(acc[0][1], ap0.x, b1);
            fma2(acc[0][2], ap0.x, b2); fma2(acc[0][3], ap0.x, b3);
            fma2(acc[1][0], ap0.y, b0); fma2(acc[1][1], ap0.y, b1);
            fma2(acc[1][2], ap0.y, b2); fma2(acc[1][3], ap0.y, b3);
            fma2(acc[2][0], ap1.x, b0); fma2(acc[2][1], ap1.x, b1);
            fma2(acc[2][2], ap1.x, b2); fma2(acc[2][3], ap1.x, b3);
            fma2(acc[3][0], ap1.y, b0); fma2(acc[3][1], ap1.y, b1);
            fma2(acc[3][2], ap1.y, b2); fma2(acc[3][3], ap1.y, b3);
            fma2(acc[4][0], ap2.x, b0); fma2(acc[4][1], ap2.x, b1);
            fma2(acc[4][2], ap2.x, b2); fma2(acc[4][3], ap2.x, b3);
            fma2(acc[5][0], ap2.y, b0); fma2(acc[5][1], ap2.y, b1);
            fma2(acc[5][2], ap2.y, b2); fma2(acc[5][3], ap2.y, b3);
            fma2(acc[6][0], ap3.x, b0); fma2(acc[6][1], ap3.x, b1);
            fma2(acc[6][2], ap3.x, b2); fma2(acc[6][3], ap3.x, b3);
            fma2(acc[7][0], ap3.y, b0); fma2(acc[7][1], ap3.y, b1);
            fma2(acc[7][2], ap3.y, b2); fma2(acc[7][3], ap3.y, b3);
        }
        if (kb < 15) {
            int nb = buf ^ 1;
            float r0[8] = {a00.x, a00.y, a00.z, a00.w, a01.x, a01.y, a01.z, a01.w};
            float r1[8] = {a10.x, a10.y, a10.z, a10.w, a11.x, a11.y, a11.z, a11.w};
            #pragma unroll
            for (int kk = 0; kk < 8; kk++)
                *(float2*)&As[nb][(akh + kk) * 132 + ar] = make_float2(r0[kk], r1[kk]);
            *(float4*)&Bs[nb][br * 68 + bc]     = bA;
            *(float4*)&Bs[nb][br * 68 + bc + 4] = bB;
            __syncthreads();
            buf = nb;
        }
    }

    // epilogue: each m-pair holds rows (2mp, 2mp+1) for 4 cols
    #pragma unroll
    for (int mp = 0; mp < 8; mp++) {
        int r0 = rowBase + tm * 16 + 2 * mp;
        float2 c0 = unpack2(acc[mp][0]);
        float2 c1 = unpack2(acc[mp][1]);
        float2 c2 = unpack2(acc[mp][2]);
        float2 c3 = unpack2(acc[mp][3]);
        if (r0 < M)
            *(float4*)&C[(size_t)r0 * N + colBase + tn * 4] =
                make_float4(c0.x, c1.x, c2.x, c3.x);
        if (r0 + 1 < M)
            *(float4*)&C[(size_t)(r0 + 1) * N + colBase + tn * 4] =
                make_float4(c0.y, c1.y, c2.y, c3.y);
    }
}

// ---------------- kernel 3: node prep --------------------------------------
__global__ __launch_bounds__(256) void k_node_xp(const float* __restrict__ bias) {
    __shared__ float red[8];
    int n = blockIdx.x;
    int j = threadIdx.x;

    float hj = (j == 0) ? 0.f : g_h[n * D + j];

    float r1 = blockSum(hj * hj, red);
    float nn = sqrtf(fmaxf(r1, EPSF));
    float sh_n = sinhf(nn) / nn;
    float xp00 = coshf(nn);
    float xp0j = (j == 0) ? xp00 : sh_n * hj;

    float bj = (j == 0) ? 0.f : bias[j];
    float c = blockSum(xp0j * bj, red);
    float fac = c / (1.f + xp00);
    float uj = bj + fac * (xp0j + ((j == 0) ? 1.f : 0.f));
    float u0 = c;

    float su2 = blockSum(uj * uj, red);
    float lin = su2 - 2.f * u0 * u0;
    float nu = sqrtf(fmaxf(lin, EPSF));
    float ch = coshf(nu), sh = sinhf(nu) / nu;
    float xpj = ch * xp0j + sh * uj;
    float xpc0 = ch * xp00 + sh * u0;

    g_xp[n * D + j] = xpj;

    float x0c = fmaxf(xpc0, 1.f + EPSF);
    float sc = acoshf(x0c) / sqrtf(x0c * x0c - 1.f);
    g_xtan[n * D + j] = (j == 0) ? 0.f : sc * xpj;
}

// ---------------- zero accumulators -----------------------------------------
__global__ void k_zero() {
    int i = blockIdx.x * blockDim.x + threadIdx.x;
    if (i < NN * D) g_H[i] = 0.f;
    if (i < NN) g_S[i] = 0.f;
}

// ---------------- edge kernel: 32 edges per block (4 per warp) --------------
__global__ __launch_bounds__(256) void k_edge(
    const float* __restrict__ eattr, const int* __restrict__ row,
    const int* __restrict__ col, const float* __restrict__ emask,
    const float* __restrict__ Wa1, const float* __restrict__ ba1,
    const float* __restrict__ Wa2, const float* __restrict__ ba2,
    const float* __restrict__ We1, const float* __restrict__ be1) {
    __shared__ float sw[8][256];
    int tid = threadIdx.x;
    sw[0][tid] = Wa1[512 * D + tid];
    sw[1][tid] = Wa1[513 * D + tid];
    sw[2][tid] = ba1[tid];
    sw[3][tid] = Wa2[tid];
    sw[4][tid] = We1[tid];
    sw[5][tid] = We1[256 * D + tid];
    sw[6][tid] = We1[257 * D + tid];
    sw[7][tid] = be1[tid];
    __syncthreads();

    int warp = tid >> 5;
    int lane = tid & 31;
    int base = lane * 8;
    float ba2v = ba2[0];

    #pragma unroll
    for (int it = 0; it < 4; it++) {
        int e = blockIdx.x * 32 + it * 8 + warp;

        int r = row[e];
        int c = col[e];
        const float* xr = g_xp + (size_t)r * D;
        const float* xc = g_xp + (size_t)c * D;

        float4 xa0 = *(const float4*)(xr + base);
        float4 xa1 = *(const float4*)(xr + base + 4);
        float4 ya0 = *(const float4*)(xc + base);
        float4 ya1 = *(const float4*)(xc + base + 4);

        float part = -(xa0.x * ya0.x + xa0.y * ya0.y + xa0.z * ya0.z + xa0.w * ya0.w +
                       xa1.x * ya1.x + xa1.y * ya1.y + xa1.z * ya1.z + xa1.w * ya1.w);
        #pragma unroll
        for (int o = 16; o > 0; o >>= 1) part += __shfl_xor_sync(0xffffffffu, part, o);

        float x0 = __shfl_sync(0xffffffffu, xa0.x, 0);
        float y0 = __shfl_sync(0xffffffffu, ya0.x, 0);

        float a = fmaxf(part + 2.f * x0 * y0, 1.f + EPSF);
        float dd = acoshf(a);
        float q = sqrtf(a * a - 1.f);
        float s = dd / q;
        float v0 = s * (y0 - a * x0);
        float beta = -v0 / (1.f + x0);
        float alpha = beta - s * a;

        float ea0 = eattr[e];
        float m = emask[e];

        const float* p1 = g_P1 + (size_t)r * D;
        const float* p2 = g_P2 + (size_t)c * D;
        float4 p1a = *(const float4*)(p1 + base);
        float4 p1b = *(const float4*)(p1 + base + 4);
        float4 p2a = *(const float4*)(p2 + base);
        float4 p2b = *(const float4*)(p2 + base + 4);
        float P1v[8] = {p1a.x, p1a.y, p1a.z, p1a.w, p1b.x, p1b.y, p1b.z, p1b.w};
        float P2v[8] = {p2a.x, p2a.y, p2a.z, p2a.w, p2b.x, p2b.y, p2b.z, p2b.w};

        float lp = 0.f;
        #pragma unroll
        for (int i = 0; i < 8; i++) {
            int j = base + i;
            float ha = P1v[i] + P2v[i] + ea0 * sw[0][j] + dd * sw[1][j] + sw[2][j];
            lp += fsilu(ha) * sw[3][j];
        }
        #pragma unroll
        for (int o = 16; o > 0; o >>= 1) lp += __shfl_xor_sync(0xffffffffu, lp, o);
        float att = m * __fdividef(1.f, 1.f + __expf(-(lp + ba2v)));

        const float* qr = g_Q + (size_t)r * D;
        const float* qc = g_Q + (size_t)c * D;
        float4 qa0 = *(const float4*)(qr + base);
        float4 qa1 = *(const float4*)(qr + base + 4);
        float4 qb0 = *(const float4*)(qc + base);
        float4 qb1 = *(const float4*)(qc + base + 4);
        float QR[8] = {qa0.x, qa0.y, qa0.z, qa0.w, qa1.x, qa1.y, qa1.z, qa1.w};
        float QC[8] = {qb0.x, qb0.y, qb0.z, qb0.w, qb1.x, qb1.y, qb1.z, qb1.w};

        float val[8];
        #pragma unroll
        for (int i = 0; i < 8; i++) {
            int j = base + i;
            float hm = alpha * QR[i] + s * QC[i] + beta * sw[4][j] +
                       ea0 * sw[5][j] + dd * sw[6][j] + sw[7][j];
            val[i] = att * fsilu(hm);
        }

        float* Hr = g_H + (size_t)r * D + base;
        asm volatile("red.global.add.v4.f32 [%0], {%1,%2,%3,%4};"
                     :: "l"(Hr), "f"(val[0]), "f"(val[1]), "f"(val[2]), "f"(val[3])
                     : "memory");
        asm volatile("red.global.add.v4.f32 [%0], {%1,%2,%3,%4};"
                     :: "l"(Hr + 4), "f"(val[4]), "f"(val[5]), "f"(val[6]), "f"(val[7])
                     : "memory");
        if (lane == 0) atomicAdd(&g_S[r], att);
    }
}

// ---------------- final node kernel -----------------------------------------
__global__ __launch_bounds__(256) void k_final(const float* __restrict__ be2,
                                               const float* __restrict__ lng,
                                               const float* __restrict__ lnb,
                                               float* __restrict__ out) {
    __shared__ float red[8];
    int n = blockIdx.x;
    int j = threadIdx.x;

    float Sv = g_S[n];
    float aggj = (j == 0) ? 0.f : (g_agg[n * D + j] + Sv * be2[j]);
    float xpj = g_xp[n * D + j];
    float xp0 = g_xp[n * D];

    float cc = blockSum(xpj * aggj, red);
    float fac = cc / (1.f + xp0);
    float supj = aggj + fac * (xpj + ((j == 0) ? 1.f : 0.f));
    float sup0 = cc;

    float su2 = blockSum(supj * supj, red);
    float lin = su2 - 2.f * sup0 * sup0;
    float nu = sqrtf(fmaxf(lin, EPSF));
    float ch = coshf(nu), sh = sinhf(nu) / nu;
    float yj = ch * xpj + sh * supj;
    float y0 = ch * xp0 + sh * sup0;

    float y0c = fmaxf(y0, 1.f + EPSF);
    float sc = acoshf(y0c) / sqrtf(y0c * y0c - 1.f);
    float xoj = (j == 0) ? 0.f : sc * yj;

    float mean = blockSum((j == 0) ? 0.f : xoj, red) * (1.f / 255.f);
    float dev = (j == 0) ? 0.f : (xoj - mean);
    float var = blockSum(dev * dev, red) * (1.f / 255.f);
    float ln = (j == 0) ? 0.f
                        : (xoj - mean) / sqrtf(var + 1e-5f) * lng[j - 1] + lnb[j - 1];

    float sl = (j == 0) ? 0.f : siluf(ln);
    float n2 = blockSum(sl * sl, red);
    float nn = sqrtf(fmaxf(n2, EPSF));
    out[n * D + j] = (j == 0) ? coshf(nn) : (sinhf(nn) / nn) * sl;
}

// ---------------- launch -----------------------------------------------------
extern "C" void kernel_launch(void* const* d_in, const int* in_sizes, int n_in,
                              void* d_out, int out_size) {
    const float* x     = (const float*)d_in[0];
    const float* eattr = (const float*)d_in[1];
    const int*   row   = (const int*)d_in[2];
    const int*   col   = (const int*)d_in[3];
    const float* emask = (const float*)d_in[5];
    const float* W_lin = (const float*)d_in[6];
    const float* bias  = (const float*)d_in[7];
    const float* W_e1  = (const float*)d_in[8];
    const float* b_e1  = (const float*)d_in[9];
    const float* W_e2  = (const float*)d_in[10];
    const float* b_e2  = (const float*)d_in[11];
    const float* W_a1  = (const float*)d_in[12];
    const float* b_a1  = (const float*)d_in[13];
    const float* W_a2  = (const float*)d_in[14];
    const float* b_a2  = (const float*)d_in[15];
    const float* ln_g  = (const float*)d_in[16];
    const float* ln_b  = (const float*)d_in[17];
    float* out = (float*)d_out;

    float *pu, *ph, *pxp, *pxt, *pQ, *pP1, *pP2, *pH, *pagg;
    cudaGetSymbolAddress((void**)&pu,   g_u);
    cudaGetSymbolAddress((void**)&ph,   g_h);
    cudaGetSymbolAddress((void**)&pxp,  g_xp);
    cudaGetSymbolAddress((void**)&pxt,  g_xtan);
    cudaGetSymbolAddress((void**)&pQ,   g_Q);
    cudaGetSymbolAddress((void**)&pP1,  g_P1);
    cudaGetSymbolAddress((void**)&pP2,  g_P2);
    cudaGetSymbolAddress((void**)&pH,   g_H);
    cudaGetSymbolAddress((void**)&pagg, g_agg);

    dim3 gElem((NN * D + 255) / 256);
    dim3 gGemm(4, (NN + 127) / 128);

    k_logmap0<<<gElem, 256>>>(x);
    sgemm_v4<<<gGemm, 128>>>(pu, W_lin, ph, NN);
    k_node_xp<<<NN, 256>>>(bias);
    sgemm_v4<<<gGemm, 128>>>(pxp, W_e1, pQ, NN);               // Q  = xp   @ W_e1[0:256]
    sgemm_v4<<<gGemm, 128>>>(pxt, W_a1, pP1, NN);              // P1 = xtan @ W_a1[0:256]
    sgemm_v4<<<gGemm, 128>>>(pxt, W_a1 + 256 * 256, pP2, NN);  // P2 = xtan @ W_a1[256:512]
    k_zero<<<gElem, 256>>>();
    k_edge<<<NE / 32, 256>>>(eattr, row, col, emask, W_a1, b_a1, W_a2, b_a2, W_e1, b_e1);
    sgemm_v4<<<gGemm, 128>>>(pH, W_e2, pagg, NN);              // agg = H @ W_e2
    k_final<<<NN, 256>>>(b_e2, ln_g, ln_b, out);
}

// round 5
// speedup vs baseline: 1.8850x; 1.8850x over previous
#include <cuda_runtime.h>
#include <math.h>

#define NN 10000
#define NE 200000
#define D  256
#define EPSF 1e-6f

typedef unsigned long long u64;

// ---------------- scratch (device globals: no allocation allowed) ----------
__device__ __align__(128) float g_u[NN * D];
__device__ __align__(128) float g_h[NN * D];
__device__ __align__(128) float g_xp[NN * D];
__device__ __align__(128) float g_xtan[NN * D];
__device__ __align__(128) float g_Q[NN * D];
__device__ __align__(128) float g_P1[NN * D];
__device__ __align__(128) float g_P2[NN * D];
__device__ __align__(128) float g_H[NN * D];
__device__ __align__(128) float g_agg[NN * D];
__device__ __align__(128) float g_S[NN];

// ---------------- packed f32x2 helpers --------------------------------------
__device__ __forceinline__ u64 dup2(float v) {
    u64 r; asm("mov.b64 %0,{%1,%1};" : "=l"(r) : "f"(v)); return r;
}
__device__ __forceinline__ void fma2(u64& c, u64 a, u64 b) {
    asm("fma.rn.f32x2 %0,%1,%2,%0;" : "+l"(c) : "l"(a), "l"(b));
}
__device__ __forceinline__ float2 unpack2(u64 v) {
    float2 f; asm("mov.b64 {%0,%1},%2;" : "=f"(f.x), "=f"(f.y) : "l"(v)); return f;
}

// ---------------- helpers ---------------------------------------------------
__device__ __forceinline__ float blockSum(float v, float* red8) {
    #pragma unroll
    for (int o = 16; o > 0; o >>= 1) v += __shfl_xor_sync(0xffffffffu, v, o);
    __syncthreads();
    if ((threadIdx.x & 31) == 0) red8[threadIdx.x >> 5] = v;
    __syncthreads();
    float r = 0.f;
    #pragma unroll
    for (int i = 0; i < 8; i++) r += red8[i];
    return r;
}

__device__ __forceinline__ float siluf(float x) { return x / (1.f + expf(-x)); }
__device__ __forceinline__ float fsilu(float x) {
    return __fdividef(x, 1.f + __expf(-x));
}

// ---------------- kernel 1: u = logmap0(x) ---------------------------------
__global__ void k_logmap0(const float* __restrict__ x) {
    int idx = blockIdx.x * blockDim.x + threadIdx.x;
    if (idx >= NN * D) return;
    int n = idx >> 8;
    int j = idx & (D - 1);
    float x0 = fmaxf(x[n * D], 1.f + EPSF);
    float outv;
    if (j == 0) {
        outv = 0.f;
    } else {
        float dd = acoshf(x0);
        float sc = dd / sqrtf(x0 * x0 - 1.f);
        outv = sc * x[idx];
    }
    g_u[idx] = outv;
}

// ---------------- SGEMM v5 body: BM=128, BN=32, BK=8, 128 thr, 8x4 micro ----
// A staged v2-style As[k][m] (column writes, conflict-free). B staged as u64
// N-pairs (float2 global load == one u64; reads = 128B broadcast, no conflicts,
// zero pack MOVs). Per warp-k: 3x LDS.128 = 1536B per 2048 lane-FMAs.
__device__ __forceinline__ void gemm_body(const float* __restrict__ A,
                                          const float* __restrict__ B,
                                          float* __restrict__ C, int M) {
    __shared__ float As[2][8][128];
    __shared__ u64   Bs[2][8][16];
    const int K = 256, N = 256;
    int tid = threadIdx.x;
    int tm = tid >> 3;          // 0..15 -> rows tm*8..tm*8+7
    int tn = tid & 7;           // 0..7  -> cols tn*4..tn*4+3
    int rowBase = blockIdx.y * 128;
    int colBase = blockIdx.x * 32;

    // A staging: thread owns row tid, 8 consecutive k
    int arow = rowBase + tid;
    bool aok = arow < M;
    const float* Aptr = A + (size_t)arow * K;
    // B staging: thread owns (brow, 2 cols)
    int brow = tid >> 4;              // 0..7
    int bcol = (tid & 15) * 2;        // 0..30
    const float* Bptr = B + (size_t)brow * N + colBase + bcol;

    const float4 z4 = make_float4(0.f, 0.f, 0.f, 0.f);

    // prologue: tile kb=0
    float4 a0 = aok ? *(const float4*)(Aptr + 0) : z4;
    float4 a1 = aok ? *(const float4*)(Aptr + 4) : z4;
    float2 b0 = *(const float2*)(Bptr);
    As[0][0][tid] = a0.x; As[0][1][tid] = a0.y; As[0][2][tid] = a0.z; As[0][3][tid] = a0.w;
    As[0][4][tid] = a1.x; As[0][5][tid] = a1.y; As[0][6][tid] = a1.z; As[0][7][tid] = a1.w;
    *(float2*)&Bs[0][brow][bcol >> 1] = b0;
    __syncthreads();

    u64 acc[8][2];
    #pragma unroll
    for (int i = 0; i < 8; i++) { acc[i][0] = 0ull; acc[i][1] = 0ull; }

    int buf = 0;
    for (int kb = 0; kb < 32; kb++) {
        if (kb < 31) {
            const float* ap = Aptr + (kb + 1) * 8;
            a0 = aok ? *(const float4*)(ap + 0) : z4;
            a1 = aok ? *(const float4*)(ap + 4) : z4;
            b0 = *(const float2*)(Bptr + (size_t)(kb + 1) * 8 * N);
        }
        #pragma unroll
        for (int k = 0; k < 8; k++) {
            float4 av0 = *(const float4*)&As[buf][k][tm * 8];
            float4 av1 = *(const float4*)&As[buf][k][tm * 8 + 4];
            ulonglong2 bv = *(const ulonglong2*)&Bs[buf][k][tn * 2];
            u64 ad;
            ad = dup2(av0.x); fma2(acc[0][0], ad, bv.x); fma2(acc[0][1], ad, bv.y);
            ad = dup2(av0.y); fma2(acc[1][0], ad, bv.x); fma2(acc[1][1], ad, bv.y);
            ad = dup2(av0.z); fma2(acc[2][0], ad, bv.x); fma2(acc[2][1], ad, bv.y);
            ad = dup2(av0.w); fma2(acc[3][0], ad, bv.x); fma2(acc[3][1], ad, bv.y);
            ad = dup2(av1.x); fma2(acc[4][0], ad, bv.x); fma2(acc[4][1], ad, bv.y);
            ad = dup2(av1.y); fma2(acc[5][0], ad, bv.x); fma2(acc[5][1], ad, bv.y);
            ad = dup2(av1.z); fma2(acc[6][0], ad, bv.x); fma2(acc[6][1], ad, bv.y);
            ad = dup2(av1.w); fma2(acc[7][0], ad, bv.x); fma2(acc[7][1], ad, bv.y);
        }
        if (kb < 31) {
            int nb = buf ^ 1;
            As[nb][0][tid] = a0.x; As[nb][1][tid] = a0.y; As[nb][2][tid] = a0.z; As[nb][3][tid] = a0.w;
            As[nb][4][tid] = a1.x; As[nb][5][tid] = a1.y; As[nb][6][tid] = a1.z; As[nb][7][tid] = a1.w;
            *(float2*)&Bs[nb][brow][bcol >> 1] = b0;
            __syncthreads();
            buf = nb;
        }
    }

    #pragma unroll
    for (int i = 0; i < 8; i++) {
        int gr = rowBase + tm * 8 + i;
        if (gr >= M) continue;
        float2 p0 = unpack2(acc[i][0]);
        float2 p1 = unpack2(acc[i][1]);
        *(float4*)&C[(size_t)gr * N + colBase + tn * 4] =
            make_float4(p0.x, p0.y, p1.x, p1.y);
    }
}

__global__ __launch_bounds__(128) void sgemm32(const float* __restrict__ A,
                                               const float* __restrict__ B,
                                               float* __restrict__ C, int M) {
    gemm_body(A, B, C, M);
}

// fused: z=0 -> Q = xp @ We1[0:256]; z=1 -> P1 = xt @ Wa1[0:256];
//        z=2 -> P2 = xt @ Wa1[256:512]
__global__ __launch_bounds__(128) void sgemm32_qp(const float* __restrict__ We1,
                                                  const float* __restrict__ Wa1) {
    int z = blockIdx.z;
    const float* A = (z == 0) ? g_xp : g_xtan;
    const float* B = (z == 0) ? We1 : (z == 1 ? Wa1 : Wa1 + 256 * 256);
    float* C = (z == 0) ? g_Q : (z == 1 ? g_P1 : g_P2);
    gemm_body(A, B, C, NN);
}

// ---------------- kernel 3: node prep --------------------------------------
__global__ __launch_bounds__(256) void k_node_xp(const float* __restrict__ bias) {
    __shared__ float red[8];
    int n = blockIdx.x;
    int j = threadIdx.x;

    float hj = (j == 0) ? 0.f : g_h[n * D + j];

    float r1 = blockSum(hj * hj, red);
    float nn = sqrtf(fmaxf(r1, EPSF));
    float sh_n = sinhf(nn) / nn;
    float xp00 = coshf(nn);
    float xp0j = (j == 0) ? xp00 : sh_n * hj;

    float bj = (j == 0) ? 0.f : bias[j];
    float c = blockSum(xp0j * bj, red);
    float fac = c / (1.f + xp00);
    float uj = bj + fac * (xp0j + ((j == 0) ? 1.f : 0.f));
    float u0 = c;

    float su2 = blockSum(uj * uj, red);
    float lin = su2 - 2.f * u0 * u0;
    float nu = sqrtf(fmaxf(lin, EPSF));
    float ch = coshf(nu), sh = sinhf(nu) / nu;
    float xpj = ch * xp0j + sh * uj;
    float xpc0 = ch * xp00 + sh * u0;

    g_xp[n * D + j] = xpj;

    float x0c = fmaxf(xpc0, 1.f + EPSF);
    float sc = acoshf(x0c) / sqrtf(x0c * x0c - 1.f);
    g_xtan[n * D + j] = (j == 0) ? 0.f : sc * xpj;
}

// ---------------- zero accumulators -----------------------------------------
__global__ void k_zero() {
    int i = blockIdx.x * blockDim.x + threadIdx.x;
    if (i < NN * D) g_H[i] = 0.f;
    if (i < NN) g_S[i] = 0.f;
}

// ---------------- edge kernel: 32 edges per block (4 per warp) --------------
__global__ __launch_bounds__(256) void k_edge(
    const float* __restrict__ eattr, const int* __restrict__ row,
    const int* __restrict__ col, const float* __restrict__ emask,
    const float* __restrict__ Wa1, const float* __restrict__ ba1,
    const float* __restrict__ Wa2, const float* __restrict__ ba2,
    const float* __restrict__ We1, const float* __restrict__ be1) {
    __shared__ float sw[8][256];
    int tid = threadIdx.x;
    sw[0][tid] = Wa1[512 * D + tid];
    sw[1][tid] = Wa1[513 * D + tid];
    sw[2][tid] = ba1[tid];
    sw[3][tid] = Wa2[tid];
    sw[4][tid] = We1[tid];
    sw[5][tid] = We1[256 * D + tid];
    sw[6][tid] = We1[257 * D + tid];
    sw[7][tid] = be1[tid];
    __syncthreads();

    int warp = tid >> 5;
    int lane = tid & 31;
    int base = lane * 8;
    float ba2v = ba2[0];

    #pragma unroll
    for (int it = 0; it < 4; it++) {
        int e = blockIdx.x * 32 + it * 8 + warp;

        int r = row[e];
        int c = col[e];
        const float* xr = g_xp + (size_t)r * D;
        const float* xc = g_xp + (size_t)c * D;

        float4 xa0 = *(const float4*)(xr + base);
        float4 xa1 = *(const float4*)(xr + base + 4);
        float4 ya0 = *(const float4*)(xc + base);
        float4 ya1 = *(const float4*)(xc + base + 4);

        float part = -(xa0.x * ya0.x + xa0.y * ya0.y + xa0.z * ya0.z + xa0.w * ya0.w +
                       xa1.x * ya1.x + xa1.y * ya1.y + xa1.z * ya1.z + xa1.w * ya1.w);
        #pragma unroll
        for (int o = 16; o > 0; o >>= 1) part += __shfl_xor_sync(0xffffffffu, part, o);

        float x0 = __shfl_sync(0xffffffffu, xa0.x, 0);
        float y0 = __shfl_sync(0xffffffffu, ya0.x, 0);

        float a = fmaxf(part + 2.f * x0 * y0, 1.f + EPSF);
        float dd = acoshf(a);
        float q = sqrtf(a * a - 1.f);
        float s = dd / q;
        float v0 = s * (y0 - a * x0);
        float beta = -v0 / (1.f + x0);
        float alpha = beta - s * a;

        float ea0 = eattr[e];
        float m = emask[e];

        const float* p1 = g_P1 + (size_t)r * D;
        const float* p2 = g_P2 + (size_t)c * D;
        float4 p1a = *(const float4*)(p1 + base);
        float4 p1b = *(const float4*)(p1 + base + 4);
        float4 p2a = *(const float4*)(p2 + base);
        float4 p2b = *(const float4*)(p2 + base + 4);
        float P1v[8] = {p1a.x, p1a.y, p1a.z, p1a.w, p1b.x, p1b.y, p1b.z, p1b.w};
        float P2v[8] = {p2a.x, p2a.y, p2a.z, p2a.w, p2b.x, p2b.y, p2b.z, p2b.w};

        float lp = 0.f;
        #pragma unroll
        for (int i = 0; i < 8; i++) {
            int j = base + i;
            float ha = P1v[i] + P2v[i] + ea0 * sw[0][j] + dd * sw[1][j] + sw[2][j];
            lp += fsilu(ha) * sw[3][j];
        }
        #pragma unroll
        for (int o = 16; o > 0; o >>= 1) lp += __shfl_xor_sync(0xffffffffu, lp, o);
        float att = m * __fdividef(1.f, 1.f + __expf(-(lp + ba2v)));

        const float* qr = g_Q + (size_t)r * D;
        const float* qc = g_Q + (size_t)c * D;
        float4 qa0 = *(const float4*)(qr + base);
        float4 qa1 = *(const float4*)(qr + base + 4);
        float4 qb0 = *(const float4*)(qc + base);
        float4 qb1 = *(const float4*)(qc + base + 4);
        float QR[8] = {qa0.x, qa0.y, qa0.z, qa0.w, qa1.x, qa1.y, qa1.z, qa1.w};
        float QC[8] = {qb0.x, qb0.y, qb0.z, qb0.w, qb1.x, qb1.y, qb1.z, qb1.w};

        float val[8];
        #pragma unroll
        for (int i = 0; i < 8; i++) {
            int j = base + i;
            float hm = alpha * QR[i] + s * QC[i] + beta * sw[4][j] +
                       ea0 * sw[5][j] + dd * sw[6][j] + sw[7][j];
            val[i] = att * fsilu(hm);
        }

        float* Hr = g_H + (size_t)r * D + base;
        asm volatile("red.global.add.v4.f32 [%0], {%1,%2,%3,%4};"
                     :: "l"(Hr), "f"(val[0]), "f"(val[1]), "f"(val[2]), "f"(val[3])
                     : "memory");
        asm volatile("red.global.add.v4.f32 [%0], {%1,%2,%3,%4};"
                     :: "l"(Hr + 4), "f"(val[4]), "f"(val[5]), "f"(val[6]), "f"(val[7])
                     : "memory");
        if (lane == 0) atomicAdd(&g_S[r], att);
    }
}

// ---------------- final node kernel -----------------------------------------
__global__ __launch_bounds__(256) void k_final(const float* __restrict__ be2,
                                               const float* __restrict__ lng,
                                               const float* __restrict__ lnb,
                                               float* __restrict__ out) {
    __shared__ float red[8];
    int n = blockIdx.x;
    int j = threadIdx.x;

    float Sv = g_S[n];
    float aggj = (j == 0) ? 0.f : (g_agg[n * D + j] + Sv * be2[j]);
    float xpj = g_xp[n * D + j];
    float xp0 = g_xp[n * D];

    float cc = blockSum(xpj * aggj, red);
    float fac = cc / (1.f + xp0);
    float supj = aggj + fac * (xpj + ((j == 0) ? 1.f : 0.f));
    float sup0 = cc;

    float su2 = blockSum(supj * supj, red);
    float lin = su2 - 2.f * sup0 * sup0;
    float nu = sqrtf(fmaxf(lin, EPSF));
    float ch = coshf(nu), sh = sinhf(nu) / nu;
    float yj = ch * xpj + sh * supj;
    float y0 = ch * xp0 + sh * sup0;

    float y0c = fmaxf(y0, 1.f + EPSF);
    float sc = acoshf(y0c) / sqrtf(y0c * y0c - 1.f);
    float xoj = (j == 0) ? 0.f : sc * yj;

    float mean = blockSum((j == 0) ? 0.f : xoj, red) * (1.f / 255.f);
    float dev = (j == 0) ? 0.f : (xoj - mean);
    float var = blockSum(dev * dev, red) * (1.f / 255.f);
    float ln = (j == 0) ? 0.f
                        : (xoj - mean) / sqrtf(var + 1e-5f) * lng[j - 1] + lnb[j - 1];

    float sl = (j == 0) ? 0.f : siluf(ln);
    float n2 = blockSum(sl * sl, red);
    float nn = sqrtf(fmaxf(n2, EPSF));
    out[n * D + j] = (j == 0) ? coshf(nn) : (sinhf(nn) / nn) * sl;
}

// ---------------- launch -----------------------------------------------------
extern "C" void kernel_launch(void* const* d_in, const int* in_sizes, int n_in,
                              void* d_out, int out_size) {
    const float* x     = (const float*)d_in[0];
    const float* eattr = (const float*)d_in[1];
    const int*   row   = (const int*)d_in[2];
    const int*   col   = (const int*)d_in[3];
    const float* emask = (const float*)d_in[5];
    const float* W_lin = (const float*)d_in[6];
    const float* bias  = (const float*)d_in[7];
    const float* W_e1  = (const float*)d_in[8];
    const float* b_e1  = (const float*)d_in[9];
    const float* W_e2  = (const float*)d_in[10];
    const float* b_e2  = (const float*)d_in[11];
    const float* W_a1  = (const float*)d_in[12];
    const float* b_a1  = (const float*)d_in[13];
    const float* W_a2  = (const float*)d_in[14];
    const float* b_a2  = (const float*)d_in[15];
    const float* ln_g  = (const float*)d_in[16];
    const float* ln_b  = (const float*)d_in[17];
    float* out = (float*)d_out;

    float *pu, *ph, *pH, *pagg;
    cudaGetSymbolAddress((void**)&pu,   g_u);
    cudaGetSymbolAddress((void**)&ph,   g_h);
    cudaGetSymbolAddress((void**)&pH,   g_H);
    cudaGetSymbolAddress((void**)&pagg, g_agg);

    dim3 gElem((NN * D + 255) / 256);
    dim3 gGemm(8, (NN + 127) / 128);          // BN=32 -> 8 col blocks
    dim3 gGemmQP(8, (NN + 127) / 128, 3);     // fused Q/P1/P2

    k_logmap0<<<gElem, 256>>>(x);
    sgemm32<<<gGemm, 128>>>(pu, W_lin, ph, NN);
    k_node_xp<<<NN, 256>>>(bias);
    sgemm32_qp<<<gGemmQP, 128>>>(W_e1, W_a1);
    k_zero<<<gElem, 256>>>();
    k_edge<<<NE / 32, 256>>>(eattr, row, col, emask, W_a1, b_a1, W_a2, b_a2, W_e1, b_e1);
    sgemm32<<<gGemm, 128>>>(pH, W_e2, pagg, NN);
    k_final<<<NN, 256>>>(b_e2, ln_g, ln_b, out);
}

// round 6
// speedup vs baseline: 1.9935x; 1.0576x over previous
#include <cuda_runtime.h>
#include <cuda_fp16.h>
#include <math.h>

#define NN 10000
#define NE 200000
#define D  256
#define EPSF 1e-6f

typedef unsigned long long u64;

// ---------------- scratch (device globals: no allocation allowed) ----------
__device__ __align__(128) float g_u[NN * D];
__device__ __align__(128) float g_h[NN * D];
__device__ __align__(128) float g_xp[NN * D];
__device__ __align__(128) float g_xtan[NN * D];
__device__ __align__(128) __half g_Qh[NN * D];
__device__ __align__(128) __half g_P1h[NN * D];
__device__ __align__(128) __half g_P2h[NN * D];
__device__ __align__(128) float g_H[NN * D];
__device__ __align__(128) float g_agg[NN * D];
__device__ __align__(128) float g_S[NN];

// ---------------- packed f32x2 helpers --------------------------------------
__device__ __forceinline__ u64 dup2(float v) {
    u64 r; asm("mov.b64 %0,{%1,%1};" : "=l"(r) : "f"(v)); return r;
}
__device__ __forceinline__ void fma2(u64& c, u64 a, u64 b) {
    asm("fma.rn.f32x2 %0,%1,%2,%0;" : "+l"(c) : "l"(a), "l"(b));
}
__device__ __forceinline__ float2 unpack2(u64 v) {
    float2 f; asm("mov.b64 {%0,%1},%2;" : "=f"(f.x), "=f"(f.y) : "l"(v)); return f;
}

// ---------------- helpers ---------------------------------------------------
__device__ __forceinline__ float blockSum(float v, float* red8) {
    #pragma unroll
    for (int o = 16; o > 0; o >>= 1) v += __shfl_xor_sync(0xffffffffu, v, o);
    __syncthreads();
    if ((threadIdx.x & 31) == 0) red8[threadIdx.x >> 5] = v;
    __syncthreads();
    float r = 0.f;
    #pragma unroll
    for (int i = 0; i < 8; i++) r += red8[i];
    return r;
}

__device__ __forceinline__ float siluf(float x) { return x / (1.f + expf(-x)); }
__device__ __forceinline__ float tanh_ap(float x) {
    float y; asm("tanh.approx.f32 %0,%1;" : "=f"(y) : "f"(x)); return y;
}
__device__ __forceinline__ float sigm_fast(float x) {
    return fmaf(0.5f, tanh_ap(0.5f * x), 0.5f);
}
__device__ __forceinline__ float silu_fast(float x) { return x * sigm_fast(x); }

// load 8 consecutive halves -> 8 floats (single LDG.128)
__device__ __forceinline__ void ld8h(const __half* p, float* o) {
    uint4 v = *(const uint4*)p;
    __half2 h0 = *(__half2*)&v.x, h1 = *(__half2*)&v.y,
            h2 = *(__half2*)&v.z, h3 = *(__half2*)&v.w;
    float2 f;
    f = __half22float2(h0); o[0] = f.x; o[1] = f.y;
    f = __half22float2(h1); o[2] = f.x; o[3] = f.y;
    f = __half22float2(h2); o[4] = f.x; o[5] = f.y;
    f = __half22float2(h3); o[6] = f.x; o[7] = f.y;
}

// ---------------- kernel 1: u = logmap0(x), plus zero accumulators ----------
__global__ void k_logmap0(const float* __restrict__ x) {
    int idx = blockIdx.x * blockDim.x + threadIdx.x;
    if (idx >= NN * D) return;
    int n = idx >> 8;
    int j = idx & (D - 1);
    float x0 = fmaxf(x[n * D], 1.f + EPSF);
    float outv;
    if (j == 0) {
        outv = 0.f;
    } else {
        float dd = acoshf(x0);
        float sc = dd / sqrtf(x0 * x0 - 1.f);
        outv = sc * x[idx];
    }
    g_u[idx] = outv;
    g_H[idx] = 0.f;
    if (idx < NN) g_S[idx] = 0.f;
}

// ---------------- SGEMM v5 body: BM=128, BN=32, BK=8, 128 thr, 8x4 micro ----
__device__ __forceinline__ void gemm_body32(const float* __restrict__ A,
                                            const float* __restrict__ B,
                                            float* __restrict__ C, int M) {
    __shared__ float As[2][8][128];
    __shared__ u64   Bs[2][8][16];
    const int K = 256, N = 256;
    int tid = threadIdx.x;
    int tm = tid >> 3;
    int tn = tid & 7;
    int rowBase = blockIdx.y * 128;
    int colBase = blockIdx.x * 32;

    int arow = rowBase + tid;
    bool aok = arow < M;
    const float* Aptr = A + (size_t)arow * K;
    int brow = tid >> 4;
    int bcol = (tid & 15) * 2;
    const float* Bptr = B + (size_t)brow * N + colBase + bcol;

    const float4 z4 = make_float4(0.f, 0.f, 0.f, 0.f);

    float4 a0 = aok ? *(const float4*)(Aptr + 0) : z4;
    float4 a1 = aok ? *(const float4*)(Aptr + 4) : z4;
    float2 b0 = *(const float2*)(Bptr);
    As[0][0][tid] = a0.x; As[0][1][tid] = a0.y; As[0][2][tid] = a0.z; As[0][3][tid] = a0.w;
    As[0][4][tid] = a1.x; As[0][5][tid] = a1.y; As[0][6][tid] = a1.z; As[0][7][tid] = a1.w;
    *(float2*)&Bs[0][brow][bcol >> 1] = b0;
    __syncthreads();

    u64 acc[8][2];
    #pragma unroll
    for (int i = 0; i < 8; i++) { acc[i][0] = 0ull; acc[i][1] = 0ull; }

    int buf = 0;
    for (int kb = 0; kb < 32; kb++) {
        if (kb < 31) {
            const float* ap = Aptr + (kb + 1) * 8;
            a0 = aok ? *(const float4*)(ap + 0) : z4;
            a1 = aok ? *(const float4*)(ap + 4) : z4;
            b0 = *(const float2*)(Bptr + (size_t)(kb + 1) * 8 * N);
        }
        #pragma unroll
        for (int k = 0; k < 8; k++) {
            float4 av0 = *(const float4*)&As[buf][k][tm * 8];
            float4 av1 = *(const float4*)&As[buf][k][tm * 8 + 4];
            ulonglong2 bv = *(const ulonglong2*)&Bs[buf][k][tn * 2];
            u64 ad;
            ad = dup2(av0.x); fma2(acc[0][0], ad, bv.x); fma2(acc[0][1], ad, bv.y);
            ad = dup2(av0.y); fma2(acc[1][0], ad, bv.x); fma2(acc[1][1], ad, bv.y);
            ad = dup2(av0.z); fma2(acc[2][0], ad, bv.x); fma2(acc[2][1], ad, bv.y);
            ad = dup2(av0.w); fma2(acc[3][0], ad, bv.x); fma2(acc[3][1], ad, bv.y);
            ad = dup2(av1.x); fma2(acc[4][0], ad, bv.x); fma2(acc[4][1], ad, bv.y);
            ad = dup2(av1.y); fma2(acc[5][0], ad, bv.x); fma2(acc[5][1], ad, bv.y);
            ad = dup2(av1.z); fma2(acc[6][0], ad, bv.x); fma2(acc[6][1], ad, bv.y);
            ad = dup2(av1.w); fma2(acc[7][0], ad, bv.x); fma2(acc[7][1], ad, bv.y);
        }
        if (kb < 31) {
            int nb = buf ^ 1;
            As[nb][0][tid] = a0.x; As[nb][1][tid] = a0.y; As[nb][2][tid] = a0.z; As[nb][3][tid] = a0.w;
            As[nb][4][tid] = a1.x; As[nb][5][tid] = a1.y; As[nb][6][tid] = a1.z; As[nb][7][tid] = a1.w;
            *(float2*)&Bs[nb][brow][bcol >> 1] = b0;
            __syncthreads();
            buf = nb;
        }
    }

    #pragma unroll
    for (int i = 0; i < 8; i++) {
        int gr = rowBase + tm * 8 + i;
        if (gr >= M) continue;
        float2 p0 = unpack2(acc[i][0]);
        float2 p1 = unpack2(acc[i][1]);
        *(float4*)&C[(size_t)gr * N + colBase + tn * 4] =
            make_float4(p0.x, p0.y, p1.x, p1.y);
    }
}

__global__ __launch_bounds__(128) void sgemm32(const float* __restrict__ A,
                                               const float* __restrict__ B,
                                               float* __restrict__ C, int M) {
    gemm_body32(A, B, C, M);
}

// ---------------- fused GEMM, BN=64, 8x8 micro-tile, fp16 output ------------
// z=0: Qh = xp @ We1[0:256]; z=1: P1h = xt @ Wa1[0:256]; z=2: P2h = Wa1[256:512]
__global__ __launch_bounds__(128) void sgemm64h_qp(const float* __restrict__ We1,
                                                   const float* __restrict__ Wa1) {
    int z = blockIdx.z;
    const float* A = (z == 0) ? g_xp : g_xtan;
    const float* B = (z == 0) ? We1 : (z == 1 ? Wa1 : Wa1 + 256 * 256);
    __half* C = (z == 0) ? g_Qh : (z == 1 ? g_P1h : g_P2h);
    const int M = NN;

    __shared__ float As[2][8][128];
    __shared__ u64   Bs[2][8][32];
    const int K = 256, N = 256;
    int tid = threadIdx.x;
    int tm = tid >> 3;          // 0..15 -> rows tm*8..+7
    int tn = tid & 7;           // 0..7  -> cols tn*8..+7
    int rowBase = blockIdx.y * 128;
    int colBase = blockIdx.x * 64;

    int arow = rowBase + tid;
    bool aok = arow < M;
    const float* Aptr = A + (size_t)arow * K;
    int brow = tid >> 4;              // 0..7
    int bcol = (tid & 15) * 4;        // 0..60
    const float* Bptr = B + (size_t)brow * N + colBase + bcol;

    const float4 z4 = make_float4(0.f, 0.f, 0.f, 0.f);

    float4 a0 = aok ? *(const float4*)(Aptr + 0) : z4;
    float4 a1 = aok ? *(const float4*)(Aptr + 4) : z4;
    float4 b0 = *(const float4*)(Bptr);
    As[0][0][tid] = a0.x; As[0][1][tid] = a0.y; As[0][2][tid] = a0.z; As[0][3][tid] = a0.w;
    As[0][4][tid] = a1.x; As[0][5][tid] = a1.y; As[0][6][tid] = a1.z; As[0][7][tid] = a1.w;
    *(float4*)&Bs[0][brow][bcol >> 1] = b0;
    __syncthreads();

    u64 acc[8][4];
    #pragma unroll
    for (int i = 0; i < 8; i++)
        #pragma unroll
        for (int j = 0; j < 4; j++) acc[i][j] = 0ull;

    int buf = 0;
    for (int kb = 0; kb < 32; kb++) {
        if (kb < 31) {
            const float* ap = Aptr + (kb + 1) * 8;
            a0 = aok ? *(const float4*)(ap + 0) : z4;
            a1 = aok ? *(const float4*)(ap + 4) : z4;
            b0 = *(const float4*)(Bptr + (size_t)(kb + 1) * 8 * N);
        }
        #pragma unroll
        for (int k = 0; k < 8; k++) {
            float4 av0 = *(const float4*)&As[buf][k][tm * 8];
            float4 av1 = *(const float4*)&As[buf][k][tm * 8 + 4];
            ulonglong2 bv0 = *(const ulonglong2*)&Bs[buf][k][tn * 4];
            ulonglong2 bv1 = *(const ulonglong2*)&Bs[buf][k][tn * 4 + 2];
            u64 ad;
            ad = dup2(av0.x);
            fma2(acc[0][0], ad, bv0.x); fma2(acc[0][1], ad, bv0.y);
            fma2(acc[0][2], ad, bv1.x); fma2(acc[0][3], ad, bv1.y);
            ad = dup2(av0.y);
            fma2(acc[1][0], ad, bv0.x); fma2(acc[1][1], ad, bv0.y);
            fma2(acc[1][2], ad, bv1.x); fma2(acc[1][3], ad, bv1.y);
            ad = dup2(av0.z);
            fma2(acc[2][0], ad, bv0.x); fma2(acc[2][1], ad, bv0.y);
            fma2(acc[2][2], ad, bv1.x); fma2(acc[2][3], ad, bv1.y);
            ad = dup2(av0.w);
            fma2(acc[3][0], ad, bv0.x); fma2(acc[3][1], ad, bv0.y);
            fma2(acc[3][2], ad, bv1.x); fma2(acc[3][3], ad, bv1.y);
            ad = dup2(av1.x);
            fma2(acc[4][0], ad, bv0.x); fma2(acc[4][1], ad, bv0.y);
            fma2(acc[4][2], ad, bv1.x); fma2(acc[4][3], ad, bv1.y);
            ad = dup2(av1.y);
            fma2(acc[5][0], ad, bv0.x); fma2(acc[5][1], ad, bv0.y);
            fma2(acc[5][2], ad, bv1.x); fma2(acc[5][3], ad, bv1.y);
            ad = dup2(av1.z);
            fma2(acc[6][0], ad, bv0.x); fma2(acc[6][1], ad, bv0.y);
            fma2(acc[6][2], ad, bv1.x); fma2(acc[6][3], ad, bv1.y);
            ad = dup2(av1.w);
            fma2(acc[7][0], ad, bv0.x); fma2(acc[7][1], ad, bv0.y);
            fma2(acc[7][2], ad, bv1.x); fma2(acc[7][3], ad, bv1.y);
        }
        if (kb < 31) {
            int nb = buf ^ 1;
            As[nb][0][tid] = a0.x; As[nb][1][tid] = a0.y; As[nb][2][tid] = a0.z; As[nb][3][tid] = a0.w;
            As[nb][4][tid] = a1.x; As[nb][5][tid] = a1.y; As[nb][6][tid] = a1.z; As[nb][7][tid] = a1.w;
            *(float4*)&Bs[nb][brow][bcol >> 1] = b0;
            __syncthreads();
            buf = nb;
        }
    }

    #pragma unroll
    for (int i = 0; i < 8; i++) {
        int gr = rowBase + tm * 8 + i;
        if (gr >= M) continue;
        float2 p0 = unpack2(acc[i][0]);
        float2 p1 = unpack2(acc[i][1]);
        float2 p2 = unpack2(acc[i][2]);
        float2 p3 = unpack2(acc[i][3]);
        __half2 h0 = __floats2half2_rn(p0.x, p0.y);
        __half2 h1 = __floats2half2_rn(p1.x, p1.y);
        __half2 h2 = __floats2half2_rn(p2.x, p2.y);
        __half2 h3 = __floats2half2_rn(p3.x, p3.y);
        uint4 o;
        o.x = *(unsigned*)&h0; o.y = *(unsigned*)&h1;
        o.z = *(unsigned*)&h2; o.w = *(unsigned*)&h3;
        *(uint4*)(C + (size_t)gr * N + colBase + tn * 8) = o;
    }
}

// ---------------- kernel 3: node prep --------------------------------------
__global__ __launch_bounds__(256) void k_node_xp(const float* __restrict__ bias) {
    __shared__ float red[8];
    int n = blockIdx.x;
    int j = threadIdx.x;

    float hj = (j == 0) ? 0.f : g_h[n * D + j];

    float r1 = blockSum(hj * hj, red);
    float nn = sqrtf(fmaxf(r1, EPSF));
    float sh_n = sinhf(nn) / nn;
    float xp00 = coshf(nn);
    float xp0j = (j == 0) ? xp00 : sh_n * hj;

    float bj = (j == 0) ? 0.f : bias[j];
    float c = blockSum(xp0j * bj, red);
    float fac = c / (1.f + xp00);
    float uj = bj + fac * (xp0j + ((j == 0) ? 1.f : 0.f));
    float u0 = c;

    float su2 = blockSum(uj * uj, red);
    float lin = su2 - 2.f * u0 * u0;
    float nu = sqrtf(fmaxf(lin, EPSF));
    float ch = coshf(nu), sh = sinhf(nu) / nu;
    float xpj = ch * xp0j + sh * uj;
    float xpc0 = ch * xp00 + sh * u0;

    g_xp[n * D + j] = xpj;

    float x0c = fmaxf(xpc0, 1.f + EPSF);
    float sc = acoshf(x0c) / sqrtf(x0c * x0c - 1.f);
    g_xtan[n * D + j] = (j == 0) ? 0.f : sc * xpj;
}

// ---------------- edge kernel: 32 edges per block (4 per warp) --------------
__global__ __launch_bounds__(256) void k_edge(
    const float* __restrict__ eattr, const int* __restrict__ row,
    const int* __restrict__ col, const float* __restrict__ emask,
    const float* __restrict__ Wa1, const float* __restrict__ ba1,
    const float* __restrict__ Wa2, const float* __restrict__ ba2,
    const float* __restrict__ We1, const float* __restrict__ be1) {
    __shared__ float sw[8][256];
    int tid = threadIdx.x;
    sw[0][tid] = Wa1[512 * D + tid];
    sw[1][tid] = Wa1[513 * D + tid];
    sw[2][tid] = ba1[tid];
    sw[3][tid] = Wa2[tid];
    sw[4][tid] = We1[tid];
    sw[5][tid] = We1[256 * D + tid];
    sw[6][tid] = We1[257 * D + tid];
    sw[7][tid] = be1[tid];
    __syncthreads();

    int warp = tid >> 5;
    int lane = tid & 31;
    int base = lane * 8;
    float ba2v = ba2[0];

    #pragma unroll
    for (int it = 0; it < 4; it++) {
        int e = blockIdx.x * 32 + it * 8 + warp;

        int r = row[e];
        int c = col[e];
        const float* xr = g_xp + (size_t)r * D;
        const float* xc = g_xp + (size_t)c * D;

        float4 xa0 = *(const float4*)(xr + base);
        float4 xa1 = *(const float4*)(xr + base + 4);
        float4 ya0 = *(const float4*)(xc + base);
        float4 ya1 = *(const float4*)(xc + base + 4);

        float part = -(xa0.x * ya0.x + xa0.y * ya0.y + xa0.z * ya0.z + xa0.w * ya0.w +
                       xa1.x * ya1.x + xa1.y * ya1.y + xa1.z * ya1.z + xa1.w * ya1.w);
        #pragma unroll
        for (int o = 16; o > 0; o >>= 1) part += __shfl_xor_sync(0xffffffffu, part, o);

        float x0 = __shfl_sync(0xffffffffu, xa0.x, 0);
        float y0 = __shfl_sync(0xffffffffu, ya0.x, 0);

        float a = fmaxf(part + 2.f * x0 * y0, 1.f + EPSF);
        float dd = acoshf(a);
        float q = sqrtf(a * a - 1.f);
        float s = dd / q;
        float v0 = s * (y0 - a * x0);
        float beta = -v0 / (1.f + x0);
        float alpha = beta - s * a;

        float ea0 = eattr[e];
        float m = emask[e];

        float P1v[8], P2v[8];
        ld8h(g_P1h + (size_t)r * D + base, P1v);
        ld8h(g_P2h + (size_t)c * D + base, P2v);

        float lp = 0.f;
        #pragma unroll
        for (int i = 0; i < 8; i++) {
            int j = base + i;
            float ha = P1v[i] + P2v[i] + ea0 * sw[0][j] + dd * sw[1][j] + sw[2][j];
            lp += silu_fast(ha) * sw[3][j];
        }
        #pragma unroll
        for (int o = 16; o > 0; o >>= 1) lp += __shfl_xor_sync(0xffffffffu, lp, o);
        float att = m * sigm_fast(lp + ba2v);

        float QR[8], QC[8];
        ld8h(g_Qh + (size_t)r * D + base, QR);
        ld8h(g_Qh + (size_t)c * D + base, QC);

        float val[8];
        #pragma unroll
        for (int i = 0; i < 8; i++) {
            int j = base + i;
            float hm = alpha * QR[i] + s * QC[i] + beta * sw[4][j] +
                       ea0 * sw[5][j] + dd * sw[6][j] + sw[7][j];
            val[i] = att * silu_fast(hm);
        }

        float* Hr = g_H + (size_t)r * D + base;
        asm volatile("red.global.add.v4.f32 [%0], {%1,%2,%3,%4};"
                     :: "l"(Hr), "f"(val[0]), "f"(val[1]), "f"(val[2]), "f"(val[3])
                     : "memory");
        asm volatile("red.global.add.v4.f32 [%0], {%1,%2,%3,%4};"
                     :: "l"(Hr + 4), "f"(val[4]), "f"(val[5]), "f"(val[6]), "f"(val[7])
                     : "memory");
        if (lane == 0) atomicAdd(&g_S[r], att);
    }
}

// ---------------- final node kernel -----------------------------------------
__global__ __launch_bounds__(256) void k_final(const float* __restrict__ be2,
                                               const float* __restrict__ lng,
                                               const float* __restrict__ lnb,
                                               float* __restrict__ out) {
    __shared__ float red[8];
    int n = blockIdx.x;
    int j = threadIdx.x;

    float Sv = g_S[n];
    float aggj = (j == 0) ? 0.f : (g_agg[n * D + j] + Sv * be2[j]);
    float xpj = g_xp[n * D + j];
    float xp0 = g_xp[n * D];

    float cc = blockSum(xpj * aggj, red);
    float fac = cc / (1.f + xp0);
    float supj = aggj + fac * (xpj + ((j == 0) ? 1.f : 0.f));
    float sup0 = cc;

    float su2 = blockSum(supj * supj, red);
    float lin = su2 - 2.f * sup0 * sup0;
    float nu = sqrtf(fmaxf(lin, EPSF));
    float ch = coshf(nu), sh = sinhf(nu) / nu;
    float yj = ch * xpj + sh * supj;
    float y0 = ch * xp0 + sh * sup0;

    float y0c = fmaxf(y0, 1.f + EPSF);
    float sc = acoshf(y0c) / sqrtf(y0c * y0c - 1.f);
    float xoj = (j == 0) ? 0.f : sc * yj;

    float mean = blockSum((j == 0) ? 0.f : xoj, red) * (1.f / 255.f);
    float dev = (j == 0) ? 0.f : (xoj - mean);
    float var = blockSum(dev * dev, red) * (1.f / 255.f);
    float ln = (j == 0) ? 0.f
                        : (xoj - mean) / sqrtf(var + 1e-5f) * lng[j - 1] + lnb[j - 1];

    float sl = (j == 0) ? 0.f : siluf(ln);
    float n2 = blockSum(sl * sl, red);
    float nn = sqrtf(fmaxf(n2, EPSF));
    out[n * D + j] = (j == 0) ? coshf(nn) : (sinhf(nn) / nn) * sl;
}

// ---------------- launch -----------------------------------------------------
extern "C" void kernel_launch(void* const* d_in, const int* in_sizes, int n_in,
                              void* d_out, int out_size) {
    const float* x     = (const float*)d_in[0];
    const float* eattr = (const float*)d_in[1];
    const int*   row   = (const int*)d_in[2];
    const int*   col   = (const int*)d_in[3];
    const float* emask = (const float*)d_in[5];
    const float* W_lin = (const float*)d_in[6];
    const float* bias  = (const float*)d_in[7];
    const float* W_e1  = (const float*)d_in[8];
    const float* b_e1  = (const float*)d_in[9];
    const float* W_e2  = (const float*)d_in[10];
    const float* b_e2  = (const float*)d_in[11];
    const float* W_a1  = (const float*)d_in[12];
    const float* b_a1  = (const float*)d_in[13];
    const float* W_a2  = (const float*)d_in[14];
    const float* b_a2  = (const float*)d_in[15];
    const float* ln_g  = (const float*)d_in[16];
    const float* ln_b  = (const float*)d_in[17];
    float* out = (float*)d_out;

    float *pu, *ph, *pH, *pagg;
    cudaGetSymbolAddress((void**)&pu,   g_u);
    cudaGetSymbolAddress((void**)&ph,   g_h);
    cudaGetSymbolAddress((void**)&pH,   g_H);
    cudaGetSymbolAddress((void**)&pagg, g_agg);

    dim3 gElem((NN * D + 255) / 256);
    dim3 gGemm32(8, (NN + 127) / 128);        // BN=32 -> 8 col blocks
    dim3 gGemmQP(4, (NN + 127) / 128, 3);     // BN=64 fused Q/P1/P2

    k_logmap0<<<gElem, 256>>>(x);                          // also zeroes H, S
    sgemm32<<<gGemm32, 128>>>(pu, W_lin, ph, NN);
    k_node_xp<<<NN, 256>>>(bias);
    sgemm64h_qp<<<gGemmQP, 128>>>(W_e1, W_a1);
    k_edge<<<NE / 32, 256>>>(eattr, row, col, emask, W_a1, b_a1, W_a2, b_a2, W_e1, b_e1);
    sgemm32<<<gGemm32, 128>>>(pH, W_e2, pagg, NN);
    k_final<<<NN, 256>>>(b_e2, ln_g, ln_b, out);
}

// round 7
// speedup vs baseline: 2.1173x; 1.0621x over previous
#include <cuda_runtime.h>
#include <cuda_fp16.h>
#include <math.h>

#define NN 10000
#define NE 200000
#define D  256
#define EPSF 1e-6f

typedef unsigned long long u64;

// ---------------- scratch (device globals: no allocation allowed) ----------
__device__ __align__(128) float g_u[NN * D];
__device__ __align__(128) float g_h[NN * D];
__device__ __align__(128) float g_xp[NN * D];
__device__ __align__(128) float g_xtan[NN * D];
__device__ __align__(128) __half g_Qh[NN * D];
__device__ __align__(128) __half g_P1h[NN * D];
__device__ __align__(128) __half g_P2h[NN * D];
__device__ __align__(128) float g_H[NN * D];
__device__ __align__(128) float g_agg[NN * D];
__device__ __align__(128) float g_S[NN];

// ---------------- packed f32x2 helpers (SIMT GEMM) ---------------------------
__device__ __forceinline__ u64 dup2(float v) {
    u64 r; asm("mov.b64 %0,{%1,%1};" : "=l"(r) : "f"(v)); return r;
}
__device__ __forceinline__ void fma2(u64& c, u64 a, u64 b) {
    asm("fma.rn.f32x2 %0,%1,%2,%0;" : "+l"(c) : "l"(a), "l"(b));
}
__device__ __forceinline__ float2 unpack2(u64 v) {
    float2 f; asm("mov.b64 {%0,%1},%2;" : "=f"(f.x), "=f"(f.y) : "l"(v)); return f;
}

// ---------------- tf32 helpers ------------------------------------------------
__device__ __forceinline__ unsigned t32(float f) {
    unsigned r; asm("cvt.rna.tf32.f32 %0,%1;" : "=r"(r) : "f"(f)); return r;
}
__device__ __forceinline__ void mma_tf32(float* d, const uint4& a, const uint2& b) {
    asm volatile(
        "mma.sync.aligned.m16n8k8.row.col.f32.tf32.tf32.f32 "
        "{%0,%1,%2,%3},{%4,%5,%6,%7},{%8,%9},{%0,%1,%2,%3};"
        : "+f"(d[0]), "+f"(d[1]), "+f"(d[2]), "+f"(d[3])
        : "r"(a.x), "r"(a.y), "r"(a.z), "r"(a.w), "r"(b.x), "r"(b.y));
}

// ---------------- misc helpers ------------------------------------------------
__device__ __forceinline__ float blockSum(float v, float* red8) {
    #pragma unroll
    for (int o = 16; o > 0; o >>= 1) v += __shfl_xor_sync(0xffffffffu, v, o);
    __syncthreads();
    if ((threadIdx.x & 31) == 0) red8[threadIdx.x >> 5] = v;
    __syncthreads();
    float r = 0.f;
    #pragma unroll
    for (int i = 0; i < 8; i++) r += red8[i];
    return r;
}
__device__ __forceinline__ float siluf(float x) { return x / (1.f + expf(-x)); }
__device__ __forceinline__ float tanh_ap(float x) {
    float y; asm("tanh.approx.f32 %0,%1;" : "=f"(y) : "f"(x)); return y;
}
__device__ __forceinline__ float sigm_fast(float x) {
    return fmaf(0.5f, tanh_ap(0.5f * x), 0.5f);
}
__device__ __forceinline__ float silu_fast(float x) { return x * sigm_fast(x); }

__device__ __forceinline__ void ld8h(const __half* p, float* o) {
    uint4 v = *(const uint4*)p;
    __half2 h0 = *(__half2*)&v.x, h1 = *(__half2*)&v.y,
            h2 = *(__half2*)&v.z, h3 = *(__half2*)&v.w;
    float2 f;
    f = __half22float2(h0); o[0] = f.x; o[1] = f.y;
    f = __half22float2(h1); o[2] = f.x; o[3] = f.y;
    f = __half22float2(h2); o[4] = f.x; o[5] = f.y;
    f = __half22float2(h3); o[6] = f.x; o[7] = f.y;
}

// ---------------- kernel 1: u = logmap0(x), plus zero accumulators ----------
__global__ void k_logmap0(const float* __restrict__ x) {
    int idx = blockIdx.x * blockDim.x + threadIdx.x;
    if (idx >= NN * D) return;
    int n = idx >> 8;
    int j = idx & (D - 1);
    float x0 = fmaxf(x[n * D], 1.f + EPSF);
    float outv;
    if (j == 0) {
        outv = 0.f;
    } else {
        float dd = acoshf(x0);
        float sc = dd / sqrtf(x0 * x0 - 1.f);
        outv = sc * x[idx];
    }
    g_u[idx] = outv;
    g_H[idx] = 0.f;
    if (idx < NN) g_S[idx] = 0.f;
}

// ---------------- SIMT SGEMM (fp32-exact path for W_lin) --------------------
__global__ __launch_bounds__(128) void sgemm32(const float* __restrict__ A,
                                               const float* __restrict__ B,
                                               float* __restrict__ C, int M) {
    __shared__ float As[2][8][128];
    __shared__ u64   Bs[2][8][16];
    const int K = 256, N = 256;
    int tid = threadIdx.x;
    int tm = tid >> 3;
    int tn = tid & 7;
    int rowBase = blockIdx.y * 128;
    int colBase = blockIdx.x * 32;

    int arow = rowBase + tid;
    bool aok = arow < M;
    const float* Aptr = A + (size_t)arow * K;
    int brow = tid >> 4;
    int bcol = (tid & 15) * 2;
    const float* Bptr = B + (size_t)brow * N + colBase + bcol;

    const float4 z4 = make_float4(0.f, 0.f, 0.f, 0.f);

    float4 a0 = aok ? *(const float4*)(Aptr + 0) : z4;
    float4 a1 = aok ? *(const float4*)(Aptr + 4) : z4;
    float2 b0 = *(const float2*)(Bptr);
    As[0][0][tid] = a0.x; As[0][1][tid] = a0.y; As[0][2][tid] = a0.z; As[0][3][tid] = a0.w;
    As[0][4][tid] = a1.x; As[0][5][tid] = a1.y; As[0][6][tid] = a1.z; As[0][7][tid] = a1.w;
    *(float2*)&Bs[0][brow][bcol >> 1] = b0;
    __syncthreads();

    u64 acc[8][2];
    #pragma unroll
    for (int i = 0; i < 8; i++) { acc[i][0] = 0ull; acc[i][1] = 0ull; }

    int buf = 0;
    for (int kb = 0; kb < 32; kb++) {
        if (kb < 31) {
            const float* ap = Aptr + (kb + 1) * 8;
            a0 = aok ? *(const float4*)(ap + 0) : z4;
            a1 = aok ? *(const float4*)(ap + 4) : z4;
            b0 = *(const float2*)(Bptr + (size_t)(kb + 1) * 8 * N);
        }
        #pragma unroll
        for (int k = 0; k < 8; k++) {
            float4 av0 = *(const float4*)&As[buf][k][tm * 8];
            float4 av1 = *(const float4*)&As[buf][k][tm * 8 + 4];
            ulonglong2 bv = *(const ulonglong2*)&Bs[buf][k][tn * 2];
            u64 ad;
            ad = dup2(av0.x); fma2(acc[0][0], ad, bv.x); fma2(acc[0][1], ad, bv.y);
            ad = dup2(av0.y); fma2(acc[1][0], ad, bv.x); fma2(acc[1][1], ad, bv.y);
            ad = dup2(av0.z); fma2(acc[2][0], ad, bv.x); fma2(acc[2][1], ad, bv.y);
            ad = dup2(av0.w); fma2(acc[3][0], ad, bv.x); fma2(acc[3][1], ad, bv.y);
            ad = dup2(av1.x); fma2(acc[4][0], ad, bv.x); fma2(acc[4][1], ad, bv.y);
            ad = dup2(av1.y); fma2(acc[5][0], ad, bv.x); fma2(acc[5][1], ad, bv.y);
            ad = dup2(av1.z); fma2(acc[6][0], ad, bv.x); fma2(acc[6][1], ad, bv.y);
            ad = dup2(av1.w); fma2(acc[7][0], ad, bv.x); fma2(acc[7][1], ad, bv.y);
        }
        if (kb < 31) {
            int nb = buf ^ 1;
            As[nb][0][tid] = a0.x; As[nb][1][tid] = a0.y; As[nb][2][tid] = a0.z; As[nb][3][tid] = a0.w;
            As[nb][4][tid] = a1.x; As[nb][5][tid] = a1.y; As[nb][6][tid] = a1.z; As[nb][7][tid] = a1.w;
            *(float2*)&Bs[nb][brow][bcol >> 1] = b0;
            __syncthreads();
            buf = nb;
        }
    }

    #pragma unroll
    for (int i = 0; i < 8; i++) {
        int gr = rowBase + tm * 8 + i;
        if (gr >= M) continue;
        float2 p0 = unpack2(acc[i][0]);
        float2 p1 = unpack2(acc[i][1]);
        *(float4*)&C[(size_t)gr * N + colBase + tn * 4] =
            make_float4(p0.x, p0.y, p1.x, p1.y);
    }
}

// ---------------- tf32 MMA GEMM: BM=64, BN=64, BK=32, 128 threads -----------
// Smem tiles are FRAGMENT-MAJOR: compute-side loads are conflict-free
// LDS.128 (A: a0..a3) / LDS.64 (B: b0,b1). Staging writes are 4x STS.128
// per thread (contiguous), with cvt.rna.tf32 applied on the fly.
struct StA { float4 f00, f01, f10, f11; };
struct StB { float2 g[8]; };

__device__ __forceinline__ void mma_stage_fetchA(StA& st, const float* pa0,
                                                 const float* pa1, bool ok0,
                                                 bool ok1) {
    const float4 z4 = make_float4(0.f, 0.f, 0.f, 0.f);
    st.f00 = ok0 ? *(const float4*)(pa0)     : z4;
    st.f01 = ok0 ? *(const float4*)(pa0 + 4) : z4;
    st.f10 = ok1 ? *(const float4*)(pa1)     : z4;
    st.f11 = ok1 ? *(const float4*)(pa1 + 4) : z4;
}
__device__ __forceinline__ void mma_stage_storeA(unsigned* dst, const StA& st) {
    const float* a00 = &st.f00.x;
    const float* a01 = &st.f01.x;
    const float* a10 = &st.f10.x;
    const float* a11 = &st.f11.x;
    #pragma unroll
    for (int dl = 0; dl < 4; dl++) {
        uint4 v = make_uint4(t32(a00[dl]), t32(a10[dl]), t32(a01[dl]), t32(a11[dl]));
        ((uint4*)dst)[dl] = v;
    }
}
__device__ __forceinline__ void mma_stage_fetchB(StB& st, const float* pb) {
    #pragma unroll
    for (int j = 0; j < 8; j++) st.g[j] = *(const float2*)(pb + j * 256);
}
__device__ __forceinline__ void mma_stage_storeB(unsigned* dst, const StB& st) {
    uint4 v0 = make_uint4(t32(st.g[0].x), t32(st.g[4].x), t32(st.g[1].x), t32(st.g[5].x));
    uint4 v1 = make_uint4(t32(st.g[2].x), t32(st.g[6].x), t32(st.g[3].x), t32(st.g[7].x));
    uint4 v2 = make_uint4(t32(st.g[0].y), t32(st.g[4].y), t32(st.g[1].y), t32(st.g[5].y));
    uint4 v3 = make_uint4(t32(st.g[2].y), t32(st.g[6].y), t32(st.g[3].y), t32(st.g[7].y));
    ((uint4*)dst)[0] = v0; ((uint4*)dst)[1] = v1;
    ((uint4*)dst)[2] = v2; ((uint4*)dst)[3] = v3;
}

template <int OUT_HALF>
__device__ __forceinline__ void mma_gemm_body(const float* __restrict__ A,
                                              const float* __restrict__ B,
                                              void* __restrict__ Cv, int M) {
    __shared__ __align__(16) unsigned smA[2][2048];
    __shared__ __align__(16) unsigned smB[2][2048];
    int tid = threadIdx.x;
    int lane = tid & 31;
    int w = tid >> 5;
    int wm = w & 1, wn = w >> 1;
    int rowBase = blockIdx.y * 64;
    int colBase = blockIdx.x * 64;

    // A staging: thread owns rows (t*16 + (tid&7)) and +8, k-cols s*8..s*8+7
    int aRow0 = rowBase + (tid >> 5) * 16 + (tid & 7);
    const float* pa0 = A + (size_t)aRow0 * 256 + ((tid >> 3) & 3) * 8;
    const float* pa1 = pa0 + 8 * 256;
    bool ok0 = aRow0 < M, ok1 = (aRow0 + 8) < M;
    // B staging: thread owns 8 k-rows (s*8..+7) x 2 n-cols
    const float* pb = B + (size_t)((tid >> 2) & 3) * 8 * 256 +
                      colBase + (tid >> 4) * 8 + 2 * (tid & 3);

    StA stA; StB stB;
    mma_stage_fetchA(stA, pa0, pa1, ok0, ok1);
    mma_stage_fetchB(stB, pb);
    mma_stage_storeA(&smA[0][tid * 16], stA);
    mma_stage_storeB(&smB[0][tid * 16], stB);
    __syncthreads();

    float d[2][4][4];
    #pragma unroll
    for (int t = 0; t < 2; t++)
        #pragma unroll
        for (int u = 0; u < 4; u++)
            #pragma unroll
            for (int c = 0; c < 4; c++) d[t][u][c] = 0.f;

    int buf = 0;
    for (int kb = 0; kb < 8; kb++) {
        if (kb < 7) {
            mma_stage_fetchA(stA, pa0 + (kb + 1) * 32, pa1 + (kb + 1) * 32, ok0, ok1);
            mma_stage_fetchB(stB, pb + (size_t)(kb + 1) * 32 * 256);
        }
        #pragma unroll
        for (int s = 0; s < 4; s++) {
            uint4 fa0 = *(const uint4*)&smA[buf][((2 * wm + 0) * 4 + s) * 128 + lane * 4];
            uint4 fa1 = *(const uint4*)&smA[buf][((2 * wm + 1) * 4 + s) * 128 + lane * 4];
            uint2 fb0 = *(const uint2*)&smB[buf][((wn * 4 + 0) * 4 + s) * 64 + lane * 2];
            uint2 fb1 = *(const uint2*)&smB[buf][((wn * 4 + 1) * 4 + s) * 64 + lane * 2];
            uint2 fb2 = *(const uint2*)&smB[buf][((wn * 4 + 2) * 4 + s) * 64 + lane * 2];
            uint2 fb3 = *(const uint2*)&smB[buf][((wn * 4 + 3) * 4 + s) * 64 + lane * 2];
            mma_tf32(d[0][0], fa0, fb0); mma_tf32(d[0][1], fa0, fb1);
            mma_tf32(d[0][2], fa0, fb2); mma_tf32(d[0][3], fa0, fb3);
            mma_tf32(d[1][0], fa1, fb0); mma_tf32(d[1][1], fa1, fb1);
            mma_tf32(d[1][2], fa1, fb2); mma_tf32(d[1][3], fa1, fb3);
        }
        if (kb < 7) {
            int nb = buf ^ 1;
            mma_stage_storeA(&smA[nb][tid * 16], stA);
            mma_stage_storeB(&smB[nb][tid * 16], stB);
            __syncthreads();
            buf = nb;
        }
    }

    // epilogue
    #pragma unroll
    for (int t = 0; t < 2; t++) {
        int r0 = rowBase + (2 * wm + t) * 16 + (lane >> 2);
        int r1 = r0 + 8;
        #pragma unroll
        for (int u = 0; u < 4; u++) {
            int c0 = colBase + wn * 32 + u * 8 + (lane & 3) * 2;
            if (OUT_HALF) {
                __half* C = (__half*)Cv;
                if (r0 < M)
                    *(__half2*)(C + (size_t)r0 * 256 + c0) =
                        __floats2half2_rn(d[t][u][0], d[t][u][1]);
                if (r1 < M)
                    *(__half2*)(C + (size_t)r1 * 256 + c0) =
                        __floats2half2_rn(d[t][u][2], d[t][u][3]);
            } else {
                float* C = (float*)Cv;
                if (r0 < M)
                    *(float2*)(C + (size_t)r0 * 256 + c0) =
                        make_float2(d[t][u][0], d[t][u][1]);
                if (r1 < M)
                    *(float2*)(C + (size_t)r1 * 256 + c0) =
                        make_float2(d[t][u][2], d[t][u][3]);
            }
        }
    }
}

// fused Q/P1/P2 (fp16 out): z=0 Qh = xp@We1[0:256]; z=1 P1h; z=2 P2h
__global__ __launch_bounds__(128) void mma_qp(const float* __restrict__ We1,
                                              const float* __restrict__ Wa1) {
    int z = blockIdx.z;
    const float* A = (z == 0) ? g_xp : g_xtan;
    const float* B = (z == 0) ? We1 : (z == 1 ? Wa1 : Wa1 + 256 * 256);
    __half* C = (z == 0) ? g_Qh : (z == 1 ? g_P1h : g_P2h);
    mma_gemm_body<1>(A, B, (void*)C, NN);
}

__global__ __launch_bounds__(128) void mma_agg(const float* __restrict__ We2) {
    mma_gemm_body<0>(g_H, We2, (void*)g_agg, NN);
}

// ---------------- kernel 3: node prep --------------------------------------
__global__ __launch_bounds__(256) void k_node_xp(const float* __restrict__ bias) {
    __shared__ float red[8];
    int n = blockIdx.x;
    int j = threadIdx.x;

    float hj = (j == 0) ? 0.f : g_h[n * D + j];

    float r1 = blockSum(hj * hj, red);
    float nn = sqrtf(fmaxf(r1, EPSF));
    float sh_n = sinhf(nn) / nn;
    float xp00 = coshf(nn);
    float xp0j = (j == 0) ? xp00 : sh_n * hj;

    float bj = (j == 0) ? 0.f : bias[j];
    float c = blockSum(xp0j * bj, red);
    float fac = c / (1.f + xp00);
    float uj = bj + fac * (xp0j + ((j == 0) ? 1.f : 0.f));
    float u0 = c;

    float su2 = blockSum(uj * uj, red);
    float lin = su2 - 2.f * u0 * u0;
    float nu = sqrtf(fmaxf(lin, EPSF));
    float ch = coshf(nu), sh = sinhf(nu) / nu;
    float xpj = ch * xp0j + sh * uj;
    float xpc0 = ch * xp00 + sh * u0;

    g_xp[n * D + j] = xpj;

    float x0c = fmaxf(xpc0, 1.f + EPSF);
    float sc = acoshf(x0c) / sqrtf(x0c * x0c - 1.f);
    g_xtan[n * D + j] = (j == 0) ? 0.f : sc * xpj;
}

// ---------------- edge kernel: 32 edges per block (4 per warp) --------------
__global__ __launch_bounds__(256) void k_edge(
    const float* __restrict__ eattr, const int* __restrict__ row,
    const int* __restrict__ col, const float* __restrict__ emask,
    const float* __restrict__ Wa1, const float* __restrict__ ba1,
    const float* __restrict__ Wa2, const float* __restrict__ ba2,
    const float* __restrict__ We1, const float* __restrict__ be1) {
    __shared__ float sw[8][256];
    int tid = threadIdx.x;
    sw[0][tid] = Wa1[512 * D + tid];
    sw[1][tid] = Wa1[513 * D + tid];
    sw[2][tid] = ba1[tid];
    sw[3][tid] = Wa2[tid];
    sw[4][tid] = We1[tid];
    sw[5][tid] = We1[256 * D + tid];
    sw[6][tid] = We1[257 * D + tid];
    sw[7][tid] = be1[tid];
    __syncthreads();

    int warp = tid >> 5;
    int lane = tid & 31;
    int base = lane * 8;
    float ba2v = ba2[0];

    #pragma unroll
    for (int it = 0; it < 4; it++) {
        int e = blockIdx.x * 32 + it * 8 + warp;

        int r = row[e];
        int c = col[e];
        const float* xr = g_xp + (size_t)r * D;
        const float* xc = g_xp + (size_t)c * D;

        float4 xa0 = *(const float4*)(xr + base);
        float4 xa1 = *(const float4*)(xr + base + 4);
        float4 ya0 = *(const float4*)(xc + base);
        float4 ya1 = *(const float4*)(xc + base + 4);

        float part = -(xa0.x * ya0.x + xa0.y * ya0.y + xa0.z * ya0.z + xa0.w * ya0.w +
                       xa1.x * ya1.x + xa1.y * ya1.y + xa1.z * ya1.z + xa1.w * ya1.w);
        #pragma unroll
        for (int o = 16; o > 0; o >>= 1) part += __shfl_xor_sync(0xffffffffu, part, o);

        float x0 = __shfl_sync(0xffffffffu, xa0.x, 0);
        float y0 = __shfl_sync(0xffffffffu, ya0.x, 0);

        float a = fmaxf(part + 2.f * x0 * y0, 1.f + EPSF);
        float dd = acoshf(a);
        float q = sqrtf(a * a - 1.f);
        float s = dd / q;
        float v0 = s * (y0 - a * x0);
        float beta = -v0 / (1.f + x0);
        float alpha = beta - s * a;

        float ea0 = eattr[e];
        float m = emask[e];

        float P1v[8], P2v[8];
        ld8h(g_P1h + (size_t)r * D + base, P1v);
        ld8h(g_P2h + (size_t)c * D + base, P2v);

        float lp = 0.f;
        #pragma unroll
        for (int i = 0; i < 8; i++) {
            int j = base + i;
            float ha = P1v[i] + P2v[i] + ea0 * sw[0][j] + dd * sw[1][j] + sw[2][j];
            lp += silu_fast(ha) * sw[3][j];
        }
        #pragma unroll
        for (int o = 16; o > 0; o >>= 1) lp += __shfl_xor_sync(0xffffffffu, lp, o);
        float att = m * sigm_fast(lp + ba2v);

        float QR[8], QC[8];
        ld8h(g_Qh + (size_t)r * D + base, QR);
        ld8h(g_Qh + (size_t)c * D + base, QC);

        float val[8];
        #pragma unroll
        for (int i = 0; i < 8; i++) {
            int j = base + i;
            float hm = alpha * QR[i] + s * QC[i] + beta * sw[4][j] +
                       ea0 * sw[5][j] + dd * sw[6][j] + sw[7][j];
            val[i] = att * silu_fast(hm);
        }

        float* Hr = g_H + (size_t)r * D + base;
        asm volatile("red.global.add.v4.f32 [%0], {%1,%2,%3,%4};"
                     :: "l"(Hr), "f"(val[0]), "f"(val[1]), "f"(val[2]), "f"(val[3])
                     : "memory");
        asm volatile("red.global.add.v4.f32 [%0], {%1,%2,%3,%4};"
                     :: "l"(Hr + 4), "f"(val[4]), "f"(val[5]), "f"(val[6]), "f"(val[7])
                     : "memory");
        if (lane == 0) atomicAdd(&g_S[r], att);
    }
}

// ---------------- final node kernel -----------------------------------------
__global__ __launch_bounds__(256) void k_final(const float* __restrict__ be2,
                                               const float* __restrict__ lng,
                                               const float* __restrict__ lnb,
                                               float* __restrict__ out) {
    __shared__ float red[8];
    int n = blockIdx.x;
    int j = threadIdx.x;

    float Sv = g_S[n];
    float aggj = (j == 0) ? 0.f : (g_agg[n * D + j] + Sv * be2[j]);
    float xpj = g_xp[n * D + j];
    float xp0 = g_xp[n * D];

    float cc = blockSum(xpj * aggj, red);
    float fac = cc / (1.f + xp0);
    float supj = aggj + fac * (xpj + ((j == 0) ? 1.f : 0.f));
    float sup0 = cc;

    float su2 = blockSum(supj * supj, red);
    float lin = su2 - 2.f * sup0 * sup0;
    float nu = sqrtf(fmaxf(lin, EPSF));
    float ch = coshf(nu), sh = sinhf(nu) / nu;
    float yj = ch * xpj + sh * supj;
    float y0 = ch * xp0 + sh * sup0;

    float y0c = fmaxf(y0, 1.f + EPSF);
    float sc = acoshf(y0c) / sqrtf(y0c * y0c - 1.f);
    float xoj = (j == 0) ? 0.f : sc * yj;

    float mean = blockSum((j == 0) ? 0.f : xoj, red) * (1.f / 255.f);
    float dev = (j == 0) ? 0.f : (xoj - mean);
    float var = blockSum(dev * dev, red) * (1.f / 255.f);
    float ln = (j == 0) ? 0.f
                        : (xoj - mean) / sqrtf(var + 1e-5f) * lng[j - 1] + lnb[j - 1];

    float sl = (j == 0) ? 0.f : siluf(ln);
    float n2 = blockSum(sl * sl, red);
    float nn = sqrtf(fmaxf(n2, EPSF));
    out[n * D + j] = (j == 0) ? coshf(nn) : (sinhf(nn) / nn) * sl;
}

// ---------------- launch -----------------------------------------------------
extern "C" void kernel_launch(void* const* d_in, const int* in_sizes, int n_in,
                              void* d_out, int out_size) {
    const float* x     = (const float*)d_in[0];
    const float* eattr = (const float*)d_in[1];
    const int*   row   = (const int*)d_in[2];
    const int*   col   = (const int*)d_in[3];
    const float* emask = (const float*)d_in[5];
    const float* W_lin = (const float*)d_in[6];
    const float* bias  = (const float*)d_in[7];
    const float* W_e1  = (const float*)d_in[8];
    const float* b_e1  = (const float*)d_in[9];
    const float* W_e2  = (const float*)d_in[10];
    const float* b_e2  = (const float*)d_in[11];
    const float* W_a1  = (const float*)d_in[12];
    const float* b_a1  = (const float*)d_in[13];
    const float* W_a2  = (const float*)d_in[14];
    const float* b_a2  = (const float*)d_in[15];
    const float* ln_g  = (const float*)d_in[16];
    const float* ln_b  = (const float*)d_in[17];
    float* out = (float*)d_out;

    float *pu, *ph;
    cudaGetSymbolAddress((void**)&pu, g_u);
    cudaGetSymbolAddress((void**)&ph, g_h);

    dim3 gElem((NN * D + 255) / 256);
    dim3 gGemm32(8, (NN + 127) / 128);
    dim3 gMmaQP(4, (NN + 63) / 64, 3);
    dim3 gMmaAgg(4, (NN + 63) / 64);

    k_logmap0<<<gElem, 256>>>(x);                       // also zeroes H, S
    sgemm32<<<gGemm32, 128>>>(pu, W_lin, ph, NN);       // fp32-exact
    k_node_xp<<<NN, 256>>>(bias);
    mma_qp<<<gMmaQP, 128>>>(W_e1, W_a1);                // tf32 tensor cores
    k_edge<<<NE / 32, 256>>>(eattr, row, col, emask, W_a1, b_a1, W_a2, b_a2, W_e1, b_e1);
    mma_agg<<<gMmaAgg, 128>>>(W_e2);                    // tf32 tensor cores
    k_final<<<NN, 256>>>(b_e2, ln_g, ln_b, out);
}

// round 8
// speedup vs baseline: 2.4689x; 1.1660x over previous
#include <cuda_runtime.h>
#include <cuda_fp16.h>
#include <math.h>

#define NN 10000
#define NE 200000
#define D  256
#define EPSF 1e-6f

typedef unsigned long long u64;

// ---------------- scratch (device globals: no allocation allowed) ----------
__device__ __align__(128) float g_u[NN * D];
__device__ __align__(128) float g_h[NN * D];
__device__ __align__(128) float g_xp[NN * D];
__device__ __align__(128) float g_xtan[NN * D];
__device__ __align__(128) __half g_Qh[NN * D];
__device__ __align__(128) __half g_P1h[NN * D];
__device__ __align__(128) __half g_P2h[NN * D];
__device__ __align__(128) float g_H[NN * D];
__device__ __align__(128) float g_agg[NN * D];
__device__ __align__(128) float g_S[NN];

// ---------------- packed f32x2 helpers (SIMT GEMM) ---------------------------
__device__ __forceinline__ u64 dup2(float v) {
    u64 r; asm("mov.b64 %0,{%1,%1};" : "=l"(r) : "f"(v)); return r;
}
__device__ __forceinline__ void fma2(u64& c, u64 a, u64 b) {
    asm("fma.rn.f32x2 %0,%1,%2,%0;" : "+l"(c) : "l"(a), "l"(b));
}
__device__ __forceinline__ float2 unpack2(u64 v) {
    float2 f; asm("mov.b64 {%0,%1},%2;" : "=f"(f.x), "=f"(f.y) : "l"(v)); return f;
}

// ---------------- tf32 helpers ------------------------------------------------
__device__ __forceinline__ unsigned t32(float f) {
    unsigned r; asm("cvt.rna.tf32.f32 %0,%1;" : "=r"(r) : "f"(f)); return r;
}
__device__ __forceinline__ void mma_tf32(float* d, const uint4& a, const uint2& b) {
    asm volatile(
        "mma.sync.aligned.m16n8k8.row.col.f32.tf32.tf32.f32 "
        "{%0,%1,%2,%3},{%4,%5,%6,%7},{%8,%9},{%0,%1,%2,%3};"
        : "+f"(d[0]), "+f"(d[1]), "+f"(d[2]), "+f"(d[3])
        : "r"(a.x), "r"(a.y), "r"(a.z), "r"(a.w), "r"(b.x), "r"(b.y));
}

// ---------------- misc helpers ------------------------------------------------
__device__ __forceinline__ float warpSum(float v) {
    #pragma unroll
    for (int o = 16; o > 0; o >>= 1) v += __shfl_xor_sync(0xffffffffu, v, o);
    return v;
}
__device__ __forceinline__ float siluf(float x) { return x / (1.f + expf(-x)); }
__device__ __forceinline__ float tanh_ap(float x) {
    float y; asm("tanh.approx.f32 %0,%1;" : "=f"(y) : "f"(x)); return y;
}
__device__ __forceinline__ float sigm_fast(float x) {
    return fmaf(0.5f, tanh_ap(0.5f * x), 0.5f);
}
__device__ __forceinline__ float silu_fast(float x) { return x * sigm_fast(x); }

__device__ __forceinline__ void ld8h(const __half* p, float* o) {
    uint4 v = *(const uint4*)p;
    __half2 h0 = *(__half2*)&v.x, h1 = *(__half2*)&v.y,
            h2 = *(__half2*)&v.z, h3 = *(__half2*)&v.w;
    float2 f;
    f = __half22float2(h0); o[0] = f.x; o[1] = f.y;
    f = __half22float2(h1); o[2] = f.x; o[3] = f.y;
    f = __half22float2(h2); o[4] = f.x; o[5] = f.y;
    f = __half22float2(h3); o[6] = f.x; o[7] = f.y;
}

// ---------------- kernel 1: u = logmap0(x), plus zero accumulators ----------
__global__ void k_logmap0(const float* __restrict__ x) {
    int idx = blockIdx.x * blockDim.x + threadIdx.x;
    if (idx >= NN * D) return;
    int n = idx >> 8;
    int j = idx & (D - 1);
    float x0 = fmaxf(x[n * D], 1.f + EPSF);
    float outv;
    if (j == 0) {
        outv = 0.f;
    } else {
        float dd = acoshf(x0);
        float sc = dd / sqrtf(x0 * x0 - 1.f);
        outv = sc * x[idx];
    }
    g_u[idx] = outv;
    g_H[idx] = 0.f;
    if (idx < NN) g_S[idx] = 0.f;
}

// ---------------- SIMT SGEMM (fp32-exact path for W_lin) --------------------
__global__ __launch_bounds__(128) void sgemm32(const float* __restrict__ A,
                                               const float* __restrict__ B,
                                               float* __restrict__ C, int M) {
    __shared__ float As[2][8][128];
    __shared__ u64   Bs[2][8][16];
    const int K = 256, N = 256;
    int tid = threadIdx.x;
    int tm = tid >> 3;
    int tn = tid & 7;
    int rowBase = blockIdx.y * 128;
    int colBase = blockIdx.x * 32;

    int arow = rowBase + tid;
    bool aok = arow < M;
    const float* Aptr = A + (size_t)arow * K;
    int brow = tid >> 4;
    int bcol = (tid & 15) * 2;
    const float* Bptr = B + (size_t)brow * N + colBase + bcol;

    const float4 z4 = make_float4(0.f, 0.f, 0.f, 0.f);

    float4 a0 = aok ? *(const float4*)(Aptr + 0) : z4;
    float4 a1 = aok ? *(const float4*)(Aptr + 4) : z4;
    float2 b0 = *(const float2*)(Bptr);
    As[0][0][tid] = a0.x; As[0][1][tid] = a0.y; As[0][2][tid] = a0.z; As[0][3][tid] = a0.w;
    As[0][4][tid] = a1.x; As[0][5][tid] = a1.y; As[0][6][tid] = a1.z; As[0][7][tid] = a1.w;
    *(float2*)&Bs[0][brow][bcol >> 1] = b0;
    __syncthreads();

    u64 acc[8][2];
    #pragma unroll
    for (int i = 0; i < 8; i++) { acc[i][0] = 0ull; acc[i][1] = 0ull; }

    int buf = 0;
    for (int kb = 0; kb < 32; kb++) {
        if (kb < 31) {
            const float* ap = Aptr + (kb + 1) * 8;
            a0 = aok ? *(const float4*)(ap + 0) : z4;
            a1 = aok ? *(const float4*)(ap + 4) : z4;
            b0 = *(const float2*)(Bptr + (size_t)(kb + 1) * 8 * N);
        }
        #pragma unroll
        for (int k = 0; k < 8; k++) {
            float4 av0 = *(const float4*)&As[buf][k][tm * 8];
            float4 av1 = *(const float4*)&As[buf][k][tm * 8 + 4];
            ulonglong2 bv = *(const ulonglong2*)&Bs[buf][k][tn * 2];
            u64 ad;
            ad = dup2(av0.x); fma2(acc[0][0], ad, bv.x); fma2(acc[0][1], ad, bv.y);
            ad = dup2(av0.y); fma2(acc[1][0], ad, bv.x); fma2(acc[1][1], ad, bv.y);
            ad = dup2(av0.z); fma2(acc[2][0], ad, bv.x); fma2(acc[2][1], ad, bv.y);
            ad = dup2(av0.w); fma2(acc[3][0], ad, bv.x); fma2(acc[3][1], ad, bv.y);
            ad = dup2(av1.x); fma2(acc[4][0], ad, bv.x); fma2(acc[4][1], ad, bv.y);
            ad = dup2(av1.y); fma2(acc[5][0], ad, bv.x); fma2(acc[5][1], ad, bv.y);
            ad = dup2(av1.z); fma2(acc[6][0], ad, bv.x); fma2(acc[6][1], ad, bv.y);
            ad = dup2(av1.w); fma2(acc[7][0], ad, bv.x); fma2(acc[7][1], ad, bv.y);
        }
        if (kb < 31) {
            int nb = buf ^ 1;
            As[nb][0][tid] = a0.x; As[nb][1][tid] = a0.y; As[nb][2][tid] = a0.z; As[nb][3][tid] = a0.w;
            As[nb][4][tid] = a1.x; As[nb][5][tid] = a1.y; As[nb][6][tid] = a1.z; As[nb][7][tid] = a1.w;
            *(float2*)&Bs[nb][brow][bcol >> 1] = b0;
            __syncthreads();
            buf = nb;
        }
    }

    #pragma unroll
    for (int i = 0; i < 8; i++) {
        int gr = rowBase + tm * 8 + i;
        if (gr >= M) continue;
        float2 p0 = unpack2(acc[i][0]);
        float2 p1 = unpack2(acc[i][1]);
        *(float4*)&C[(size_t)gr * N + colBase + tn * 4] =
            make_float4(p0.x, p0.y, p1.x, p1.y);
    }
}

// ---------------- tf32 MMA GEMM: BM=64, BN=128, BK=32, 128 threads -----------
// Warp tile 32x64 (B reuse doubled vs 32x32). Fragment-major smem; B stored as
// two 64-col halves, each with the proven per-half layout.
struct StA { float4 f00, f01, f10, f11; };
struct StB { float2 g[8]; };

__device__ __forceinline__ void mma_stage_fetchA(StA& st, const float* pa0,
                                                 const float* pa1, bool ok0,
                                                 bool ok1) {
    const float4 z4 = make_float4(0.f, 0.f, 0.f, 0.f);
    st.f00 = ok0 ? *(const float4*)(pa0)     : z4;
    st.f01 = ok0 ? *(const float4*)(pa0 + 4) : z4;
    st.f10 = ok1 ? *(const float4*)(pa1)     : z4;
    st.f11 = ok1 ? *(const float4*)(pa1 + 4) : z4;
}
__device__ __forceinline__ void mma_stage_storeA(unsigned* dst, const StA& st) {
    const float* a00 = &st.f00.x;
    const float* a01 = &st.f01.x;
    const float* a10 = &st.f10.x;
    const float* a11 = &st.f11.x;
    #pragma unroll
    for (int dl = 0; dl < 4; dl++) {
        uint4 v = make_uint4(t32(a00[dl]), t32(a10[dl]), t32(a01[dl]), t32(a11[dl]));
        ((uint4*)dst)[dl] = v;
    }
}
__device__ __forceinline__ void mma_stage_fetchB(StB& st, const float* pb) {
    #pragma unroll
    for (int j = 0; j < 8; j++) st.g[j] = *(const float2*)(pb + j * 256);
}
__device__ __forceinline__ void mma_stage_storeB(unsigned* dst, const StB& st) {
    uint4 v0 = make_uint4(t32(st.g[0].x), t32(st.g[4].x), t32(st.g[1].x), t32(st.g[5].x));
    uint4 v1 = make_uint4(t32(st.g[2].x), t32(st.g[6].x), t32(st.g[3].x), t32(st.g[7].x));
    uint4 v2 = make_uint4(t32(st.g[0].y), t32(st.g[4].y), t32(st.g[1].y), t32(st.g[5].y));
    uint4 v3 = make_uint4(t32(st.g[2].y), t32(st.g[6].y), t32(st.g[3].y), t32(st.g[7].y));
    ((uint4*)dst)[0] = v0; ((uint4*)dst)[1] = v1;
    ((uint4*)dst)[2] = v2; ((uint4*)dst)[3] = v3;
}

template <int OUT_HALF>
__device__ __forceinline__ void mma_gemm_body(const float* __restrict__ A,
                                              const float* __restrict__ B,
                                              void* __restrict__ Cv, int M) {
    __shared__ __align__(16) unsigned smA[2][2048];
    __shared__ __align__(16) unsigned smB[2][4096];
    int tid = threadIdx.x;
    int lane = tid & 31;
    int w = tid >> 5;
    int wm = w & 1, wn = w >> 1;
    int rowBase = blockIdx.y * 64;
    int colBase = blockIdx.x * 128;

    int aRow0 = rowBase + (tid >> 5) * 16 + (tid & 7);
    const float* pa0 = A + (size_t)aRow0 * 256 + ((tid >> 3) & 3) * 8;
    const float* pa1 = pa0 + 8 * 256;
    bool ok0 = aRow0 < M, ok1 = (aRow0 + 8) < M;
    const float* pb = B + (size_t)((tid >> 2) & 3) * 8 * 256 +
                      colBase + (tid >> 4) * 8 + 2 * (tid & 3);

    StA stA; StB stB0, stB1;
    mma_stage_fetchA(stA, pa0, pa1, ok0, ok1);
    mma_stage_fetchB(stB0, pb);
    mma_stage_fetchB(stB1, pb + 64);
    mma_stage_storeA(&smA[0][tid * 16], stA);
    mma_stage_storeB(&smB[0][tid * 16], stB0);
    mma_stage_storeB(&smB[0][2048 + tid * 16], stB1);
    __syncthreads();

    float d[2][8][4];
    #pragma unroll
    for (int t = 0; t < 2; t++)
        #pragma unroll
        for (int u = 0; u < 8; u++)
            #pragma unroll
            for (int c = 0; c < 4; c++) d[t][u][c] = 0.f;

    int buf = 0;
    for (int kb = 0; kb < 8; kb++) {
        if (kb < 7) {
            mma_stage_fetchA(stA, pa0 + (kb + 1) * 32, pa1 + (kb + 1) * 32, ok0, ok1);
            mma_stage_fetchB(stB0, pb + (size_t)(kb + 1) * 32 * 256);
            mma_stage_fetchB(stB1, pb + (size_t)(kb + 1) * 32 * 256 + 64);
        }
        #pragma unroll
        for (int s = 0; s < 4; s++) {
            uint4 fa0 = *(const uint4*)&smA[buf][((2 * wm + 0) * 4 + s) * 128 + lane * 4];
            uint4 fa1 = *(const uint4*)&smA[buf][((2 * wm + 1) * 4 + s) * 128 + lane * 4];
            uint2 fb[8];
            #pragma unroll
            for (int u = 0; u < 8; u++)
                fb[u] = *(const uint2*)&smB[buf][wn * 2048 + (u * 4 + s) * 64 + lane * 2];
            #pragma unroll
            for (int u = 0; u < 8; u++) {
                mma_tf32(d[0][u], fa0, fb[u]);
                mma_tf32(d[1][u], fa1, fb[u]);
            }
        }
        if (kb < 7) {
            int nb = buf ^ 1;
            mma_stage_storeA(&smA[nb][tid * 16], stA);
            mma_stage_storeB(&smB[nb][tid * 16], stB0);
            mma_stage_storeB(&smB[nb][2048 + tid * 16], stB1);
            __syncthreads();
            buf = nb;
        }
    }

    #pragma unroll
    for (int t = 0; t < 2; t++) {
        int r0 = rowBase + (2 * wm + t) * 16 + (lane >> 2);
        int r1 = r0 + 8;
        #pragma unroll
        for (int u = 0; u < 8; u++) {
            int c0 = colBase + wn * 64 + u * 8 + (lane & 3) * 2;
            if (OUT_HALF) {
                __half* C = (__half*)Cv;
                if (r0 < M)
                    *(__half2*)(C + (size_t)r0 * 256 + c0) =
                        __floats2half2_rn(d[t][u][0], d[t][u][1]);
                if (r1 < M)
                    *(__half2*)(C + (size_t)r1 * 256 + c0) =
                        __floats2half2_rn(d[t][u][2], d[t][u][3]);
            } else {
                float* C = (float*)Cv;
                if (r0 < M)
                    *(float2*)(C + (size_t)r0 * 256 + c0) =
                        make_float2(d[t][u][0], d[t][u][1]);
                if (r1 < M)
                    *(float2*)(C + (size_t)r1 * 256 + c0) =
                        make_float2(d[t][u][2], d[t][u][3]);
            }
        }
    }
}

__global__ __launch_bounds__(128, 3) void mma_qp(const float* __restrict__ We1,
                                                 const float* __restrict__ Wa1) {
    int z = blockIdx.z;
    const float* A = (z == 0) ? g_xp : g_xtan;
    const float* B = (z == 0) ? We1 : (z == 1 ? Wa1 : Wa1 + 256 * 256);
    __half* C = (z == 0) ? g_Qh : (z == 1 ? g_P1h : g_P2h);
    mma_gemm_body<1>(A, B, (void*)C, NN);
}

__global__ __launch_bounds__(128, 3) void mma_agg(const float* __restrict__ We2) {
    mma_gemm_body<0>(g_H, We2, (void*)g_agg, NN);
}

// ---------------- node prep: one warp per node (shfl-only reductions) --------
__global__ __launch_bounds__(256) void k_node_xp(const float* __restrict__ bias) {
    int node = blockIdx.x * 8 + (threadIdx.x >> 5);
    int lane = threadIdx.x & 31;
    int base = lane * 8;

    float h[8];
    const float* hp = g_h + (size_t)node * D + base;
    *(float4*)&h[0] = *(const float4*)(hp);
    *(float4*)&h[4] = *(const float4*)(hp + 4);
    if (lane == 0) h[0] = 0.f;

    float acc = 0.f;
    #pragma unroll
    for (int i = 0; i < 8; i++) acc += h[i] * h[i];
    float r1 = warpSum(acc);
    float nn = sqrtf(fmaxf(r1, EPSF));
    float sh_n = sinhf(nn) / nn;
    float xp00 = coshf(nn);
    float xp0[8];
    #pragma unroll
    for (int i = 0; i < 8; i++) xp0[i] = sh_n * h[i];
    if (lane == 0) xp0[0] = xp00;

    float b[8];
    *(float4*)&b[0] = *(const float4*)(bias + base);
    *(float4*)&b[4] = *(const float4*)(bias + base + 4);
    if (lane == 0) b[0] = 0.f;

    acc = 0.f;
    #pragma unroll
    for (int i = 0; i < 8; i++) acc += xp0[i] * b[i];
    float c = warpSum(acc);
    float fac = c / (1.f + xp00);
    float u[8];
    #pragma unroll
    for (int i = 0; i < 8; i++) u[i] = b[i] + fac * xp0[i];
    if (lane == 0) u[0] += fac;   // + fac * 1 (time-axis unit)

    acc = 0.f;
    #pragma unroll
    for (int i = 0; i < 8; i++) acc += u[i] * u[i];
    float su2 = warpSum(acc);
    float lin = su2 - 2.f * c * c;
    float nu = sqrtf(fmaxf(lin, EPSF));
    float ch = coshf(nu), sh = sinhf(nu) / nu;

    float xp[8];
    #pragma unroll
    for (int i = 0; i < 8; i++) xp[i] = ch * xp0[i] + sh * u[i];
    float* xpp = g_xp + (size_t)node * D + base;
    *(float4*)(xpp)     = *(float4*)&xp[0];
    *(float4*)(xpp + 4) = *(float4*)&xp[4];

    float xpc0 = ch * xp00 + sh * c;
    float x0c = fmaxf(xpc0, 1.f + EPSF);
    float sc = acoshf(x0c) / sqrtf(x0c * x0c - 1.f);
    float xt[8];
    #pragma unroll
    for (int i = 0; i < 8; i++) xt[i] = sc * xp[i];
    if (lane == 0) xt[0] = 0.f;
    float* xtp = g_xtan + (size_t)node * D + base;
    *(float4*)(xtp)     = *(float4*)&xt[0];
    *(float4*)(xtp + 4) = *(float4*)&xt[4];
}

// ---------------- edge kernel: 32 edges per block (4 per warp) --------------
__global__ __launch_bounds__(256) void k_edge(
    const float* __restrict__ eattr, const int* __restrict__ row,
    const int* __restrict__ col, const float* __restrict__ emask,
    const float* __restrict__ Wa1, const float* __restrict__ ba1,
    const float* __restrict__ Wa2, const float* __restrict__ ba2,
    const float* __restrict__ We1, const float* __restrict__ be1) {
    __shared__ float sw[8][256];
    int tid = threadIdx.x;
    sw[0][tid] = Wa1[512 * D + tid];
    sw[1][tid] = Wa1[513 * D + tid];
    sw[2][tid] = ba1[tid];
    sw[3][tid] = Wa2[tid];
    sw[4][tid] = We1[tid];
    sw[5][tid] = We1[256 * D + tid];
    sw[6][tid] = We1[257 * D + tid];
    sw[7][tid] = be1[tid];
    __syncthreads();

    int warp = tid >> 5;
    int lane = tid & 31;
    int base = lane * 8;
    float ba2v = ba2[0];

    #pragma unroll
    for (int it = 0; it < 4; it++) {
        int e = blockIdx.x * 32 + it * 8 + warp;

        int r = row[e];
        int c = col[e];
        const float* xr = g_xp + (size_t)r * D;
        const float* xc = g_xp + (size_t)c * D;

        float4 xa0 = *(const float4*)(xr + base);
        float4 xa1 = *(const float4*)(xr + base + 4);
        float4 ya0 = *(const float4*)(xc + base);
        float4 ya1 = *(const float4*)(xc + base + 4);

        float part = -(xa0.x * ya0.x + xa0.y * ya0.y + xa0.z * ya0.z + xa0.w * ya0.w +
                       xa1.x * ya1.x + xa1.y * ya1.y + xa1.z * ya1.z + xa1.w * ya1.w);
        part = warpSum(part);

        float x0 = __shfl_sync(0xffffffffu, xa0.x, 0);
        float y0 = __shfl_sync(0xffffffffu, ya0.x, 0);

        float a = fmaxf(part + 2.f * x0 * y0, 1.f + EPSF);
        float dd = acoshf(a);
        float q = sqrtf(a * a - 1.f);
        float s = dd / q;
        float v0 = s * (y0 - a * x0);
        float beta = -v0 / (1.f + x0);
        float alpha = beta - s * a;

        float ea0 = eattr[e];
        float m = emask[e];

        float P1v[8], P2v[8];
        ld8h(g_P1h + (size_t)r * D + base, P1v);
        ld8h(g_P2h + (size_t)c * D + base, P2v);

        float lp = 0.f;
        #pragma unroll
        for (int i = 0; i < 8; i++) {
            int j = base + i;
            float ha = P1v[i] + P2v[i] + ea0 * sw[0][j] + dd * sw[1][j] + sw[2][j];
            lp += silu_fast(ha) * sw[3][j];
        }
        lp = warpSum(lp);
        float att = m * sigm_fast(lp + ba2v);

        float QR[8], QC[8];
        ld8h(g_Qh + (size_t)r * D + base, QR);
        ld8h(g_Qh + (size_t)c * D + base, QC);

        float val[8];
        #pragma unroll
        for (int i = 0; i < 8; i++) {
            int j = base + i;
            float hm = alpha * QR[i] + s * QC[i] + beta * sw[4][j] +
                       ea0 * sw[5][j] + dd * sw[6][j] + sw[7][j];
            val[i] = att * silu_fast(hm);
        }

        float* Hr = g_H + (size_t)r * D + base;
        asm volatile("red.global.add.v4.f32 [%0], {%1,%2,%3,%4};"
                     :: "l"(Hr), "f"(val[0]), "f"(val[1]), "f"(val[2]), "f"(val[3])
                     : "memory");
        asm volatile("red.global.add.v4.f32 [%0], {%1,%2,%3,%4};"
                     :: "l"(Hr + 4), "f"(val[4]), "f"(val[5]), "f"(val[6]), "f"(val[7])
                     : "memory");
        if (lane == 0) atomicAdd(&g_S[r], att);
    }
}

// ---------------- final node kernel: one warp per node -----------------------
__global__ __launch_bounds__(256) void k_final(const float* __restrict__ be2,
                                               const float* __restrict__ lng,
                                               const float* __restrict__ lnb,
                                               float* __restrict__ out) {
    int node = blockIdx.x * 8 + (threadIdx.x >> 5);
    int lane = threadIdx.x & 31;
    int base = lane * 8;

    float Sv = g_S[node];
    float ag[8], be[8], xp[8];
    const float* agp = g_agg + (size_t)node * D + base;
    *(float4*)&ag[0] = *(const float4*)(agp);
    *(float4*)&ag[4] = *(const float4*)(agp + 4);
    *(float4*)&be[0] = *(const float4*)(be2 + base);
    *(float4*)&be[4] = *(const float4*)(be2 + base + 4);
    const float* xpp = g_xp + (size_t)node * D + base;
    *(float4*)&xp[0] = *(const float4*)(xpp);
    *(float4*)&xp[4] = *(const float4*)(xpp + 4);

    #pragma unroll
    for (int i = 0; i < 8; i++) ag[i] += Sv * be[i];
    if (lane == 0) ag[0] = 0.f;

    float xp0 = __shfl_sync(0xffffffffu, xp[0], 0);

    float acc = 0.f;
    #pragma unroll
    for (int i = 0; i < 8; i++) acc += xp[i] * ag[i];
    float cc = warpSum(acc);
    float fac = cc / (1.f + xp0);
    float sup[8];
    #pragma unroll
    for (int i = 0; i < 8; i++) sup[i] = ag[i] + fac * xp[i];
    if (lane == 0) sup[0] += fac;

    acc = 0.f;
    #pragma unroll
    for (int i = 0; i < 8; i++) acc += sup[i] * sup[i];
    float su2 = warpSum(acc);
    float lin = su2 - 2.f * cc * cc;
    float nu = sqrtf(fmaxf(lin, EPSF));
    float ch = coshf(nu), sh = sinhf(nu) / nu;

    float y[8];
    #pragma unroll
    for (int i = 0; i < 8; i++) y[i] = ch * xp[i] + sh * sup[i];
    float y0 = ch * xp0 + sh * cc;

    float y0c = fmaxf(y0, 1.f + EPSF);
    float sc = acoshf(y0c) / sqrtf(y0c * y0c - 1.f);
    float xo[8];
    #pragma unroll
    for (int i = 0; i < 8; i++) xo[i] = sc * y[i];
    if (lane == 0) xo[0] = 0.f;

    acc = 0.f;
    #pragma unroll
    for (int i = 0; i < 8; i++) acc += xo[i];
    float mean = warpSum(acc) * (1.f / 255.f);
    float dev[8];
    #pragma unroll
    for (int i = 0; i < 8; i++) dev[i] = xo[i] - mean;
    if (lane == 0) dev[0] = 0.f;
    acc = 0.f;
    #pragma unroll
    for (int i = 0; i < 8; i++) acc += dev[i] * dev[i];
    float var = warpSum(acc) * (1.f / 255.f);
    float inv = rsqrtf(var + 1e-5f) * 0.f + 1.f / sqrtf(var + 1e-5f);

    float sl[8];
    #pragma unroll
    for (int i = 0; i < 8; i++) {
        int j = base + i;
        float lg = (j > 0) ? lng[j - 1] : 0.f;
        float lb = (j > 0) ? lnb[j - 1] : 0.f;
        float ln = dev[i] * inv * lg + lb;
        sl[i] = siluf(ln);
    }
    if (lane == 0) sl[0] = 0.f;

    acc = 0.f;
    #pragma unroll
    for (int i = 0; i < 8; i++) acc += sl[i] * sl[i];
    float n2 = warpSum(acc);
    float nn = sqrtf(fmaxf(n2, EPSF));
    float shn = sinhf(nn) / nn;

    float o[8];
    #pragma unroll
    for (int i = 0; i < 8; i++) o[i] = shn * sl[i];
    if (lane == 0) o[0] = coshf(nn);
    float* op = out + (size_t)node * D + base;
    *(float4*)(op)     = *(float4*)&o[0];
    *(float4*)(op + 4) = *(float4*)&o[4];
}

// ---------------- launch -----------------------------------------------------
extern "C" void kernel_launch(void* const* d_in, const int* in_sizes, int n_in,
                              void* d_out, int out_size) {
    const float* x     = (const float*)d_in[0];
    const float* eattr = (const float*)d_in[1];
    const int*   row   = (const int*)d_in[2];
    const int*   col   = (const int*)d_in[3];
    const float* emask = (const float*)d_in[5];
    const float* W_lin = (const float*)d_in[6];
    const float* bias  = (const float*)d_in[7];
    const float* W_e1  = (const float*)d_in[8];
    const float* b_e1  = (const float*)d_in[9];
    const float* W_e2  = (const float*)d_in[10];
    const float* b_e2  = (const float*)d_in[11];
    const float* W_a1  = (const float*)d_in[12];
    const float* b_a1  = (const float*)d_in[13];
    const float* W_a2  = (const float*)d_in[14];
    const float* b_a2  = (const float*)d_in[15];
    const float* ln_g  = (const float*)d_in[16];
    const float* ln_b  = (const float*)d_in[17];
    float* out = (float*)d_out;

    float *pu, *ph;
    cudaGetSymbolAddress((void**)&pu, g_u);
    cudaGetSymbolAddress((void**)&ph, g_h);

    dim3 gElem((NN * D + 255) / 256);
    dim3 gGemm32(8, (NN + 127) / 128);
    dim3 gMmaQP(2, (NN + 63) / 64, 3);
    dim3 gMmaAgg(2, (NN + 63) / 64);

    k_logmap0<<<gElem, 256>>>(x);                       // also zeroes H, S
    sgemm32<<<gGemm32, 128>>>(pu, W_lin, ph, NN);       // fp32-exact
    k_node_xp<<<NN / 8, 256>>>(bias);
    mma_qp<<<gMmaQP, 128>>>(W_e1, W_a1);                // tf32, 32x64 warp tile
    k_edge<<<NE / 32, 256>>>(eattr, row, col, emask, W_a1, b_a1, W_a2, b_a2, W_e1, b_e1);
    mma_agg<<<gMmaAgg, 128>>>(W_e2);                    // tf32, 32x64 warp tile
    k_final<<<NN / 8, 256>>>(b_e2, ln_g, ln_b, out);
}